// round 1
// baseline (speedup 1.0000x reference)
#include <cuda_runtime.h>
#include <math.h>

// ---- problem constants ----
#define NTOK 844      // B*T = 2*422
#define TSEQ 422
#define BSZ  2
#define CDIM 768
#define NH   32
#define HSD  24
#define NE   32
#define F4D  3072
#define NL   2
#define NV   100

// ---- device scratch (no allocations allowed) ----
__device__ float g_x  [NTOK * CDIM];
__device__ float g_h  [NTOK * CDIM];
__device__ float g_qkv[NTOK * 3 * CDIM];
__device__ float g_att[NTOK * CDIM];
__device__ float g_wp [CDIM * 3 * CDIM];
__device__ float g_gates[NTOK * NE];
__device__ float g_hid[(size_t)NTOK * NE * F4D];   // 844*98304 floats ~332MB
__device__ float g_eo [(size_t)NTOK * NE * CDIM];  // 844*24576 floats ~83MB

// ======================= embedding =======================
__global__ void embed_kernel(const int* __restrict__ idx,
                             const float* __restrict__ tok,
                             const float* __restrict__ pos,
                             float* __restrict__ x) {
    int n = blockIdx.x;
    int t = n % TSEQ;
    int v = idx[n];
    for (int c = threadIdx.x; c < CDIM; c += blockDim.x)
        x[n * CDIM + c] = tok[v * CDIM + c] + pos[t * CDIM + c];
}

// ======================= layernorm =======================
__global__ void ln_kernel(const float* __restrict__ x,
                          const float* __restrict__ g,
                          const float* __restrict__ b,
                          float* __restrict__ out) {
    int n = blockIdx.x;
    int tid = threadIdx.x;
    __shared__ float s1[256], s2[256];
    const float* xr = x + (size_t)n * CDIM;
    float a = 0.f, q = 0.f;
    for (int c = tid; c < CDIM; c += 256) { float v = xr[c]; a += v; q += v * v; }
    s1[tid] = a; s2[tid] = q;
    __syncthreads();
    for (int s = 128; s > 0; s >>= 1) {
        if (tid < s) { s1[tid] += s1[tid + s]; s2[tid] += s2[tid + s]; }
        __syncthreads();
    }
    float mean = s1[0] * (1.f / CDIM);
    float var  = s2[0] * (1.f / CDIM) - mean * mean;
    float r = rsqrtf(var + 1e-5f);
    for (int c = tid; c < CDIM; c += 256)
        out[(size_t)n * CDIM + c] = (xr[c] - mean) * r * g[c] + b[c];
}

// ======================= pack Wq/Wk/Wv -> [C, 3*C] =======================
// wp[c][which*768 + h*HS + s] = W{q,k,v}[h,c,s]
__global__ void pack_qkv_kernel(const float* __restrict__ Wq,
                                const float* __restrict__ Wk,
                                const float* __restrict__ Wv,
                                float* __restrict__ wp) {
    int i = blockIdx.x * blockDim.x + threadIdx.x;
    if (i >= CDIM * CDIM) return;
    int c = i / CDIM;
    int j = i % CDIM;          // h*HS + s
    int h = j / HSD, s = j % HSD;
    size_t src = ((size_t)h * CDIM + c) * HSD + s;
    size_t dst = (size_t)c * (3 * CDIM) + j;
    wp[dst]              = Wq[src];
    wp[dst + CDIM]       = Wk[src];
    wp[dst + 2 * CDIM]   = Wv[src];
}

// ======================= generic tiled SGEMM =======================
// C[m, j] = epilogue( sum_k A[m, e*expA + k] * B[e*expB + k*ldb + (j - e*cpe)] )
// e = j / cpe.  bias indexed by global j.
// EP: 0 = plain, 1 = +bias, 2 = accumulate (+= acc + bias), 3 = gelu(acc + bias)
__device__ __forceinline__ float gelu_exact(float v) {
    return 0.5f * v * (1.f + erff(v * 0.70710678118654752f));
}

template <int EP>
__global__ void __launch_bounds__(256)
sgemm_kernel(const float* __restrict__ A, int lda, int expA,
             const float* __restrict__ B, size_t expB, int ldb,
             const float* __restrict__ bias,
             float* __restrict__ C, int ldc,
             int M, int N, int K, int cpe) {
    __shared__ float As[64][17];
    __shared__ float Bs[16][64];
    int tid = threadIdx.x;
    int jTile = blockIdx.x * 64;
    int mTile = blockIdx.y * 64;
    int e   = jTile / cpe;
    int jl0 = jTile - e * cpe;
    const float* Ab = A + (size_t)e * expA;
    const float* Bb = B + (size_t)e * expB;
    int tx = tid & 15, ty = tid >> 4;

    float acc[4][4];
#pragma unroll
    for (int r = 0; r < 4; r++)
#pragma unroll
        for (int c = 0; c < 4; c++) acc[r][c] = 0.f;

    int aRow = tid >> 2;        // 0..63
    int aK   = (tid & 3) * 4;   // 0,4,8,12
    int bJ   = tid & 63;
    int bK0  = tid >> 6;        // 0..3

    for (int k0 = 0; k0 < K; k0 += 16) {
        // load A tile (64 x 16), K always multiple of 16, float4 aligned
        int m = mTile + aRow;
        if (m < M) {
            float4 av = *(const float4*)(Ab + (size_t)m * lda + k0 + aK);
            As[aRow][aK + 0] = av.x; As[aRow][aK + 1] = av.y;
            As[aRow][aK + 2] = av.z; As[aRow][aK + 3] = av.w;
        } else {
            As[aRow][aK + 0] = 0.f; As[aRow][aK + 1] = 0.f;
            As[aRow][aK + 2] = 0.f; As[aRow][aK + 3] = 0.f;
        }
        // load B tile (16 x 64)
#pragma unroll
        for (int i = 0; i < 4; i++) {
            int kk = bK0 + i * 4;
            Bs[kk][bJ] = (jTile + bJ < N)
                ? Bb[(size_t)(k0 + kk) * ldb + jl0 + bJ] : 0.f;
        }
        __syncthreads();
#pragma unroll
        for (int k = 0; k < 16; k++) {
            float4 bv = *(const float4*)&Bs[k][tx * 4];
            float a0 = As[ty * 4 + 0][k];
            float a1 = As[ty * 4 + 1][k];
            float a2 = As[ty * 4 + 2][k];
            float a3 = As[ty * 4 + 3][k];
            acc[0][0] += a0 * bv.x; acc[0][1] += a0 * bv.y; acc[0][2] += a0 * bv.z; acc[0][3] += a0 * bv.w;
            acc[1][0] += a1 * bv.x; acc[1][1] += a1 * bv.y; acc[1][2] += a1 * bv.z; acc[1][3] += a1 * bv.w;
            acc[2][0] += a2 * bv.x; acc[2][1] += a2 * bv.y; acc[2][2] += a2 * bv.z; acc[2][3] += a2 * bv.w;
            acc[3][0] += a3 * bv.x; acc[3][1] += a3 * bv.y; acc[3][2] += a3 * bv.z; acc[3][3] += a3 * bv.w;
        }
        __syncthreads();
    }

#pragma unroll
    for (int r = 0; r < 4; r++) {
        int m = mTile + ty * 4 + r;
        if (m >= M) continue;
#pragma unroll
        for (int c = 0; c < 4; c++) {
            int j = jTile + tx * 4 + c;
            if (j >= N) continue;
            float v = acc[r][c];
            if (EP >= 1) v += bias[j];
            if (EP == 3) v = gelu_exact(v);
            size_t o = (size_t)m * ldc + j;
            if (EP == 2) C[o] += v; else C[o] = v;
        }
    }
}

// ======================= attention (one block per b,h,t) =======================
__global__ void attn_kernel(const float* __restrict__ qkv,
                            float* __restrict__ att) {
    int t = blockIdx.x, h = blockIdx.y, b = blockIdx.z;
    int tid = threadIdx.x;                       // 128 threads
    __shared__ float sc[TSEQ];
    __shared__ float qs[HSD];
    __shared__ float red[128];
    __shared__ float part[5 * HSD];

    int n0 = b * TSEQ;
    const float* Q = qkv + (size_t)(n0 + t) * (3 * CDIM) + h * HSD;
    if (tid < HSD) qs[tid] = Q[tid];
    __syncthreads();

    const float scale = 0.20412414523193154f;    // 1/sqrt(24)
    float lmax = -1e30f;
    for (int u = tid; u <= t; u += 128) {
        const float* Kp = qkv + (size_t)(n0 + u) * (3 * CDIM) + CDIM + h * HSD;
        float d = 0.f;
#pragma unroll
        for (int s = 0; s < HSD; s++) d += qs[s] * Kp[s];
        d *= scale;
        sc[u] = d;
        lmax = fmaxf(lmax, d);
    }
    red[tid] = lmax;
    __syncthreads();
    for (int s = 64; s > 0; s >>= 1) {
        if (tid < s) red[tid] = fmaxf(red[tid], red[tid + s]);
        __syncthreads();
    }
    float mx = red[0];
    __syncthreads();

    float lsum = 0.f;
    for (int u = tid; u <= t; u += 128) {
        float ev = expf(sc[u] - mx);
        sc[u] = ev;
        lsum += ev;
    }
    red[tid] = lsum;
    __syncthreads();
    for (int s = 64; s > 0; s >>= 1) {
        if (tid < s) red[tid] += red[tid + s];
        __syncthreads();
    }
    float inv = 1.f / red[0];
    __syncthreads();

    if (tid < 120) {
        int s = tid % HSD, g = tid / HSD;        // g in 0..4
        float a = 0.f;
        for (int u = g; u <= t; u += 5) {
            const float* Vp = qkv + (size_t)(n0 + u) * (3 * CDIM) + 2 * CDIM + h * HSD;
            a += sc[u] * Vp[s];
        }
        part[g * HSD + s] = a;
    }
    __syncthreads();
    if (tid < HSD) {
        float a = part[tid] + part[HSD + tid] + part[2 * HSD + tid]
                + part[3 * HSD + tid] + part[4 * HSD + tid];
        att[(size_t)(n0 + t) * CDIM + h * HSD + tid] = a * inv;
    }
}

// ======================= gate softmax (one warp per token) =======================
__global__ void gate_kernel(const float* __restrict__ h2,
                            const float* __restrict__ gw,
                            const float* __restrict__ gb,
                            float* __restrict__ gates) {
    int n = blockIdx.x;
    int e = threadIdx.x;                          // 32 threads
    const float* hr = h2 + (size_t)n * CDIM;
    float acc = gb[e];
    for (int c = 0; c < CDIM; c++) acc += hr[c] * gw[c * NE + e];
    float mx = acc;
    for (int o = 16; o > 0; o >>= 1) mx = fmaxf(mx, __shfl_xor_sync(0xFFFFFFFFu, mx, o));
    float ex = expf(acc - mx);
    float sm = ex;
    for (int o = 16; o > 0; o >>= 1) sm += __shfl_xor_sync(0xFFFFFFFFu, sm, o);
    gates[n * NE + e] = ex / sm;
}

// ======================= MoE combine: x += sum_e g[n,e] * eo[n,e,:] =======================
__global__ void combine_kernel(const float* __restrict__ eo,
                               const float* __restrict__ gates,
                               float* __restrict__ x) {
    int n = blockIdx.x;
    __shared__ float gs[NE];
    if (threadIdx.x < NE) gs[threadIdx.x] = gates[n * NE + threadIdx.x];
    __syncthreads();
    for (int c = threadIdx.x; c < CDIM; c += blockDim.x) {
        float a = 0.f;
        const float* er = eo + (size_t)n * (NE * CDIM) + c;
#pragma unroll 8
        for (int e = 0; e < NE; e++) a += gs[e] * er[e * CDIM];
        x[(size_t)n * CDIM + c] += a;
    }
}

// ======================= launch =======================
extern "C" void kernel_launch(void* const* d_in, const int* in_sizes, int n_in,
                              void* d_out, int out_size) {
    const int*   idx    = (const int*)  d_in[0];
    const float* tok    = (const float*)d_in[1];
    const float* pos    = (const float*)d_in[2];
    const float* ln1_g  = (const float*)d_in[3];
    const float* ln1_b  = (const float*)d_in[4];
    const float* Wq     = (const float*)d_in[5];
    const float* Wk     = (const float*)d_in[6];
    const float* Wv     = (const float*)d_in[7];
    const float* Wo     = (const float*)d_in[8];
    const float* bo     = (const float*)d_in[9];
    const float* ln2_g  = (const float*)d_in[10];
    const float* ln2_b  = (const float*)d_in[11];
    const float* gate_w = (const float*)d_in[12];
    const float* gate_b = (const float*)d_in[13];
    const float* W1     = (const float*)d_in[14];
    const float* b1     = (const float*)d_in[15];
    const float* W2     = (const float*)d_in[16];
    const float* b2     = (const float*)d_in[17];
    const float* lnf_g  = (const float*)d_in[18];
    const float* lnf_b  = (const float*)d_in[19];
    const float* lm_w   = (const float*)d_in[20];
    const float* lm_b   = (const float*)d_in[21];
    float* out = (float*)d_out;

    float *x, *h, *qkv, *att, *wp, *gates, *hid, *eo;
    cudaGetSymbolAddress((void**)&x,     g_x);
    cudaGetSymbolAddress((void**)&h,     g_h);
    cudaGetSymbolAddress((void**)&qkv,   g_qkv);
    cudaGetSymbolAddress((void**)&att,   g_att);
    cudaGetSymbolAddress((void**)&wp,    g_wp);
    cudaGetSymbolAddress((void**)&gates, g_gates);
    cudaGetSymbolAddress((void**)&hid,   g_hid);
    cudaGetSymbolAddress((void**)&eo,    g_eo);

    auto gemm_grid = [](int M, int N) { return dim3((N + 63) / 64, (M + 63) / 64); };

    embed_kernel<<<NTOK, 256>>>(idx, tok, pos, x);

    for (int l = 0; l < NL; l++) {
        // --- attention ---
        ln_kernel<<<NTOK, 256>>>(x, ln1_g + l * CDIM, ln1_b + l * CDIM, h);
        pack_qkv_kernel<<<(CDIM * CDIM + 255) / 256, 256>>>(
            Wq + (size_t)l * NH * CDIM * HSD,
            Wk + (size_t)l * NH * CDIM * HSD,
            Wv + (size_t)l * NH * CDIM * HSD, wp);
        sgemm_kernel<0><<<gemm_grid(NTOK, 3 * CDIM), 256>>>(
            h, CDIM, 0, wp, 0, 3 * CDIM, nullptr,
            qkv, 3 * CDIM, NTOK, 3 * CDIM, CDIM, 3 * CDIM);
        attn_kernel<<<dim3(TSEQ, NH, BSZ), 128>>>(qkv, att);
        sgemm_kernel<2><<<gemm_grid(NTOK, CDIM), 256>>>(
            att, CDIM, 0, Wo + (size_t)l * CDIM * CDIM, 0, CDIM, bo + l * CDIM,
            x, CDIM, NTOK, CDIM, CDIM, CDIM);

        // --- MoE ---
        ln_kernel<<<NTOK, 256>>>(x, ln2_g + l * CDIM, ln2_b + l * CDIM, h);
        gate_kernel<<<NTOK, 32>>>(h, gate_w + (size_t)l * CDIM * NE,
                                  gate_b + l * NE, gates);
        // up-projection + GELU, all 32 experts in one launch
        sgemm_kernel<3><<<gemm_grid(NTOK, NE * F4D), 256>>>(
            h, CDIM, 0,
            W1 + (size_t)l * NE * CDIM * F4D, (size_t)CDIM * F4D, F4D,
            b1 + (size_t)l * NE * F4D,
            hid, NE * F4D, NTOK, NE * F4D, CDIM, F4D);
        // down-projection, all 32 experts in one launch
        sgemm_kernel<1><<<gemm_grid(NTOK, NE * CDIM), 256>>>(
            hid, NE * F4D, F4D,
            W2 + (size_t)l * NE * F4D * CDIM, (size_t)F4D * CDIM, CDIM,
            b2 + (size_t)l * NE * CDIM,
            eo, NE * CDIM, NTOK, NE * CDIM, F4D, CDIM);
        combine_kernel<<<NTOK, 256>>>(eo, gates, x);
    }

    // --- final LN + lm head ---
    ln_kernel<<<NTOK, 256>>>(x, lnf_g, lnf_b, h);
    sgemm_kernel<1><<<gemm_grid(NTOK, NV), 256>>>(
        h, CDIM, 0, lm_w, 0, NV, lm_b,
        out, NV, NTOK, NV, CDIM, NV);
}

// round 3
// speedup vs baseline: 2.0889x; 2.0889x over previous
#include <cuda_runtime.h>
#include <cuda_bf16.h>
#include <math.h>
#include <stdint.h>

// ---- problem constants ----
#define NTOK 844      // B*T = 2*422
#define TSEQ 422
#define BSZ  2
#define CDIM 768
#define NH   32
#define HSD  24
#define NE   32
#define F4D  3072
#define NL   2
#define NV   100

// ---- device scratch ----
__device__ float g_x  [NTOK * CDIM];
__device__ float g_h  [NTOK * CDIM];
__device__ float g_qkv[NTOK * 3 * CDIM];
__device__ float g_att[NTOK * CDIM];
__device__ float g_wp [CDIM * 3 * CDIM];
__device__ float g_gates[NTOK * NE];
__device__ float g_hid[(size_t)NTOK * NE * F4D];   // fp32 ~332MB
__device__ float g_eo [(size_t)NTOK * NE * CDIM];  // fp32 ~83MB

// ======================= helpers =======================
__device__ __forceinline__ float gelu_exact(float v) {
    return 0.5f * v * (1.f + erff(v * 0.70710678118654752f));
}

// split two fp32 into bf16 hi-pair and lo-pair (packed u32 each)
__device__ __forceinline__ uint2 split2(float x, float y) {
    __nv_bfloat16 hx = __float2bfloat16_rn(x), hy = __float2bfloat16_rn(y);
    __nv_bfloat16 lx = __float2bfloat16_rn(x - __bfloat162float(hx));
    __nv_bfloat16 ly = __float2bfloat16_rn(y - __bfloat162float(hy));
    __nv_bfloat162 h; h.x = hx; h.y = hy;
    __nv_bfloat162 l; l.x = lx; l.y = ly;
    return make_uint2(*(unsigned*)&h, *(unsigned*)&l);
}

__device__ __forceinline__ void mma16816(float* d, const unsigned* a, const unsigned* b) {
    asm volatile(
        "mma.sync.aligned.m16n8k16.row.col.f32.bf16.bf16.f32 "
        "{%0,%1,%2,%3}, {%4,%5,%6,%7}, {%8,%9}, {%0,%1,%2,%3};"
        : "+f"(d[0]), "+f"(d[1]), "+f"(d[2]), "+f"(d[3])
        : "r"(a[0]), "r"(a[1]), "r"(a[2]), "r"(a[3]), "r"(b[0]), "r"(b[1]));
}

// ======================= bf16x3 HMMA GEMM =======================
// C_e[m, n] = epilogue( sum_k A_e[m,k] * W_e[k,n] ), 128x128 tile per CTA.
// A_e = A + e*aExp (row stride lda); W_e = W + e*wExp (row stride ldw).
// grid.x = Mtiles*Ntiles (nt fast), grid.y = expert.
// EP: 0 plain, 1 +bias, 2 C += (acc+bias), 3 gelu(acc+bias)
// SMEM per buffer: Ahi[128][40] Alo[128][40] bf16, Bhi[128][34] Blo[128][34] bf16
#define A_STR 40
#define B_STR 34
#define ABUF_ELEMS (128 * A_STR)
#define BBUF_ELEMS (128 * B_STR)
#define BUF_BYTES (2 * (ABUF_ELEMS + BBUF_ELEMS) * 2)   // 37888
#define MM_SMEM (2 * BUF_BYTES)                          // 75776

template <int EP>
__global__ void __launch_bounds__(256)
moe_mma(const float* __restrict__ A, long long lda, long long aExp,
        const float* __restrict__ W, long long wExp, long long ldw,
        const float* __restrict__ bias, long long bExp,
        float* __restrict__ C, long long ldc, long long cExp,
        int M, int Ntiles, int KC) {
    extern __shared__ char sm[];
    const int tid = threadIdx.x, wid = tid >> 5, lane = tid & 31;
    const int g = lane >> 2, tg = lane & 3;
    const int wm = wid >> 2, wn = wid & 3;          // warp tile 64M x 32N
    const int e = blockIdx.y;
    const int nt = blockIdx.x % Ntiles, mt = blockIdx.x / Ntiles;
    const int n0 = nt * 128, m0 = mt * 128;

    const float* Ab = A + (size_t)e * aExp;
    const float* Wb = W + (size_t)e * wExp;

    float acc[4][4][4];
#pragma unroll
    for (int i = 0; i < 4; i++)
#pragma unroll
        for (int j = 0; j < 4; j++)
#pragma unroll
            for (int r = 0; r < 4; r++) acc[i][j][r] = 0.f;

    // per-thread fill coords
    const int aRow = tid >> 3, aK4 = tid & 7;       // A: 4 float4 per thread
    const int bK2 = tid >> 5, bN4 = tid & 31;       // B: 2 items (k-pair x 4n) per thread

    float4 ra[4], rb0[2], rb1[2];

    auto ldgA = [&](int k0) {
#pragma unroll
        for (int i = 0; i < 4; i++) {
            int row = aRow + i * 32;
            int m = m0 + row;
            ra[i] = (m < M) ? *(const float4*)(Ab + (size_t)m * lda + k0 + aK4 * 4)
                            : make_float4(0.f, 0.f, 0.f, 0.f);
        }
    };
    auto ldgB = [&](int k0) {
#pragma unroll
        for (int i = 0; i < 2; i++) {
            int k2 = bK2 + i * 8;
            const float* p = Wb + (size_t)(k0 + k2 * 2) * ldw + n0 + bN4 * 4;
            rb0[i] = *(const float4*)p;
            rb1[i] = *(const float4*)(p + ldw);
        }
    };
    auto sts = [&](int buf) {
        __nv_bfloat16* Ahi = (__nv_bfloat16*)(sm + buf * BUF_BYTES);
        __nv_bfloat16* Alo = Ahi + ABUF_ELEMS;
        __nv_bfloat16* Bhi = Alo + ABUF_ELEMS;
        __nv_bfloat16* Blo = Bhi + BBUF_ELEMS;
#pragma unroll
        for (int i = 0; i < 4; i++) {
            int row = aRow + i * 32;
            uint2 p0 = split2(ra[i].x, ra[i].y);
            uint2 p1 = split2(ra[i].z, ra[i].w);
            uint2 hh = make_uint2(p0.x, p1.x);
            uint2 ll = make_uint2(p0.y, p1.y);
            *(uint2*)&Ahi[row * A_STR + aK4 * 4] = hh;
            *(uint2*)&Alo[row * A_STR + aK4 * 4] = ll;
        }
#pragma unroll
        for (int i = 0; i < 2; i++) {
            int k2 = bK2 + i * 8;
            const float* q0 = (const float*)&rb0[i];
            const float* q1 = (const float*)&rb1[i];
#pragma unroll
            for (int j = 0; j < 4; j++) {
                int n = bN4 * 4 + j;
                uint2 p = split2(q0[j], q1[j]);
                *(unsigned*)&Bhi[n * B_STR + k2 * 2] = p.x;
                *(unsigned*)&Blo[n * B_STR + k2 * 2] = p.y;
            }
        }
    };

    // prologue: fill buffer 0
    ldgA(0); ldgB(0);
    sts(0);
    __syncthreads();

    for (int c = 0; c < KC; ++c) {
        const int buf = c & 1;
        if (c + 1 < KC) { ldgA((c + 1) * 32); ldgB((c + 1) * 32); }

        const __nv_bfloat16* Ahi = (const __nv_bfloat16*)(sm + buf * BUF_BYTES);
        const __nv_bfloat16* Alo = Ahi + ABUF_ELEMS;
        const __nv_bfloat16* Bhi = Alo + ABUF_ELEMS;
        const __nv_bfloat16* Blo = Bhi + BBUF_ELEMS;

#pragma unroll
        for (int ks = 0; ks < 2; ks++) {
            const int kb = ks * 16;
            unsigned bh[4][2], bl[4][2];
#pragma unroll
            for (int ni = 0; ni < 4; ni++) {
                int rn = wn * 32 + ni * 8 + g;
                int o = rn * B_STR + kb + tg * 2;
                bh[ni][0] = *(const unsigned*)&Bhi[o];
                bh[ni][1] = *(const unsigned*)&Bhi[o + 8];
                bl[ni][0] = *(const unsigned*)&Blo[o];
                bl[ni][1] = *(const unsigned*)&Blo[o + 8];
            }
#pragma unroll
            for (int mi = 0; mi < 4; mi++) {
                int rm = wm * 64 + mi * 16 + g;
                int o = rm * A_STR + kb + tg * 2;
                unsigned ah[4], al[4];
                ah[0] = *(const unsigned*)&Ahi[o];
                ah[1] = *(const unsigned*)&Ahi[o + 8 * A_STR];
                ah[2] = *(const unsigned*)&Ahi[o + 8];
                ah[3] = *(const unsigned*)&Ahi[o + 8 * A_STR + 8];
                al[0] = *(const unsigned*)&Alo[o];
                al[1] = *(const unsigned*)&Alo[o + 8 * A_STR];
                al[2] = *(const unsigned*)&Alo[o + 8];
                al[3] = *(const unsigned*)&Alo[o + 8 * A_STR + 8];
#pragma unroll
                for (int ni = 0; ni < 4; ni++) {
                    mma16816(acc[mi][ni], ah, bh[ni]);
                    mma16816(acc[mi][ni], ah, bl[ni]);
                    mma16816(acc[mi][ni], al, bh[ni]);
                }
            }
        }

        if (c + 1 < KC) sts(buf ^ 1);
        __syncthreads();
    }

    // ---- epilogue ----
#pragma unroll
    for (int mi = 0; mi < 4; mi++) {
        int r0 = m0 + wm * 64 + mi * 16 + g;
#pragma unroll
        for (int ni = 0; ni < 4; ni++) {
            int j = wn * 32 + ni * 8 + tg * 2;       // local col in [0,128)
            float b0 = 0.f, b1 = 0.f;
            if (EP >= 1) {
                b0 = bias[(size_t)e * bExp + n0 + j];
                b1 = bias[(size_t)e * bExp + n0 + j + 1];
            }
#pragma unroll
            for (int half = 0; half < 2; half++) {
                int r = r0 + half * 8;
                if (r >= M) continue;
                float v0 = acc[mi][ni][half * 2 + 0] + b0;
                float v1 = acc[mi][ni][half * 2 + 1] + b1;
                if (EP == 3) { v0 = gelu_exact(v0); v1 = gelu_exact(v1); }
                float* p = C + (size_t)e * cExp + (size_t)r * ldc + n0 + j;
                if (EP == 2) { p[0] += v0; p[1] += v1; }
                else {
                    float2 o2 = make_float2(v0, v1);
                    *(float2*)p = o2;
                }
            }
        }
    }
}

// ======================= embedding =======================
__global__ void embed_kernel(const int* __restrict__ idx,
                             const float* __restrict__ tok,
                             const float* __restrict__ pos,
                             float* __restrict__ x) {
    int n = blockIdx.x;
    int t = n % TSEQ;
    int v = idx[n];
    for (int c = threadIdx.x; c < CDIM; c += blockDim.x)
        x[n * CDIM + c] = tok[v * CDIM + c] + pos[t * CDIM + c];
}

// ======================= layernorm =======================
__global__ void ln_kernel(const float* __restrict__ x,
                          const float* __restrict__ g,
                          const float* __restrict__ b,
                          float* __restrict__ out) {
    int n = blockIdx.x;
    int tid = threadIdx.x;
    __shared__ float s1[256], s2[256];
    const float* xr = x + (size_t)n * CDIM;
    float a = 0.f, q = 0.f;
    for (int c = tid; c < CDIM; c += 256) { float v = xr[c]; a += v; q += v * v; }
    s1[tid] = a; s2[tid] = q;
    __syncthreads();
    for (int s = 128; s > 0; s >>= 1) {
        if (tid < s) { s1[tid] += s1[tid + s]; s2[tid] += s2[tid + s]; }
        __syncthreads();
    }
    float mean = s1[0] * (1.f / CDIM);
    float var  = s2[0] * (1.f / CDIM) - mean * mean;
    float r = rsqrtf(var + 1e-5f);
    for (int c = tid; c < CDIM; c += 256)
        out[(size_t)n * CDIM + c] = (xr[c] - mean) * r * g[c] + b[c];
}

// ======================= pack Wq/Wk/Wv -> [C, 3*C] =======================
__global__ void pack_qkv_kernel(const float* __restrict__ Wq,
                                const float* __restrict__ Wk,
                                const float* __restrict__ Wv,
                                float* __restrict__ wp) {
    int i = blockIdx.x * blockDim.x + threadIdx.x;
    if (i >= CDIM * CDIM) return;
    int c = i / CDIM;
    int j = i % CDIM;
    int h = j / HSD, s = j % HSD;
    size_t src = ((size_t)h * CDIM + c) * HSD + s;
    size_t dst = (size_t)c * (3 * CDIM) + j;
    wp[dst]            = Wq[src];
    wp[dst + CDIM]     = Wk[src];
    wp[dst + 2 * CDIM] = Wv[src];
}

// ======================= scalar tiled SGEMM (lm head) =======================
template <int EP>
__global__ void __launch_bounds__(256)
sgemm_kernel(const float* __restrict__ A, int lda,
             const float* __restrict__ B, int ldb,
             const float* __restrict__ bias,
             float* __restrict__ C, int ldc,
             int M, int N, int K) {
    __shared__ float As[64][17];
    __shared__ float Bs[16][64];
    int tid = threadIdx.x;
    int jTile = blockIdx.x * 64;
    int mTile = blockIdx.y * 64;
    int tx = tid & 15, ty = tid >> 4;

    float acc[4][4];
#pragma unroll
    for (int r = 0; r < 4; r++)
#pragma unroll
        for (int c = 0; c < 4; c++) acc[r][c] = 0.f;

    int aRow = tid >> 2;
    int aK   = (tid & 3) * 4;
    int bJ   = tid & 63;
    int bK0  = tid >> 6;

    for (int k0 = 0; k0 < K; k0 += 16) {
        int m = mTile + aRow;
        if (m < M) {
            float4 av = *(const float4*)(A + (size_t)m * lda + k0 + aK);
            As[aRow][aK + 0] = av.x; As[aRow][aK + 1] = av.y;
            As[aRow][aK + 2] = av.z; As[aRow][aK + 3] = av.w;
        } else {
            As[aRow][aK + 0] = 0.f; As[aRow][aK + 1] = 0.f;
            As[aRow][aK + 2] = 0.f; As[aRow][aK + 3] = 0.f;
        }
#pragma unroll
        for (int i = 0; i < 4; i++) {
            int kk = bK0 + i * 4;
            Bs[kk][bJ] = (jTile + bJ < N)
                ? B[(size_t)(k0 + kk) * ldb + jTile + bJ] : 0.f;
        }
        __syncthreads();
#pragma unroll
        for (int k = 0; k < 16; k++) {
            float4 bv = *(const float4*)&Bs[k][tx * 4];
            float a0 = As[ty * 4 + 0][k];
            float a1 = As[ty * 4 + 1][k];
            float a2 = As[ty * 4 + 2][k];
            float a3 = As[ty * 4 + 3][k];
            acc[0][0] += a0 * bv.x; acc[0][1] += a0 * bv.y; acc[0][2] += a0 * bv.z; acc[0][3] += a0 * bv.w;
            acc[1][0] += a1 * bv.x; acc[1][1] += a1 * bv.y; acc[1][2] += a1 * bv.z; acc[1][3] += a1 * bv.w;
            acc[2][0] += a2 * bv.x; acc[2][1] += a2 * bv.y; acc[2][2] += a2 * bv.z; acc[2][3] += a2 * bv.w;
            acc[3][0] += a3 * bv.x; acc[3][1] += a3 * bv.y; acc[3][2] += a3 * bv.z; acc[3][3] += a3 * bv.w;
        }
        __syncthreads();
    }

#pragma unroll
    for (int r = 0; r < 4; r++) {
        int m = mTile + ty * 4 + r;
        if (m >= M) continue;
#pragma unroll
        for (int c = 0; c < 4; c++) {
            int j = jTile + tx * 4 + c;
            if (j >= N) continue;
            float v = acc[r][c];
            if (EP >= 1) v += bias[j];
            size_t o = (size_t)m * ldc + j;
            if (EP == 2) C[o] += v; else C[o] = v;
        }
    }
}

// ======================= attention =======================
__global__ void attn_kernel(const float* __restrict__ qkv,
                            float* __restrict__ att) {
    int t = blockIdx.x, h = blockIdx.y, b = blockIdx.z;
    int tid = threadIdx.x;
    __shared__ float sc[TSEQ];
    __shared__ float qs[HSD];
    __shared__ float red[128];
    __shared__ float part[5 * HSD];

    int n0 = b * TSEQ;
    const float* Q = qkv + (size_t)(n0 + t) * (3 * CDIM) + h * HSD;
    if (tid < HSD) qs[tid] = Q[tid];
    __syncthreads();

    const float scale = 0.20412414523193154f;
    float lmax = -1e30f;
    for (int u = tid; u <= t; u += 128) {
        const float* Kp = qkv + (size_t)(n0 + u) * (3 * CDIM) + CDIM + h * HSD;
        float d = 0.f;
#pragma unroll
        for (int s = 0; s < HSD; s++) d += qs[s] * Kp[s];
        d *= scale;
        sc[u] = d;
        lmax = fmaxf(lmax, d);
    }
    red[tid] = lmax;
    __syncthreads();
    for (int s = 64; s > 0; s >>= 1) {
        if (tid < s) red[tid] = fmaxf(red[tid], red[tid + s]);
        __syncthreads();
    }
    float mx = red[0];
    __syncthreads();

    float lsum = 0.f;
    for (int u = tid; u <= t; u += 128) {
        float ev = expf(sc[u] - mx);
        sc[u] = ev;
        lsum += ev;
    }
    red[tid] = lsum;
    __syncthreads();
    for (int s = 64; s > 0; s >>= 1) {
        if (tid < s) red[tid] += red[tid + s];
        __syncthreads();
    }
    float inv = 1.f / red[0];
    __syncthreads();

    if (tid < 120) {
        int s = tid % HSD, g = tid / HSD;
        float a = 0.f;
        for (int u = g; u <= t; u += 5) {
            const float* Vp = qkv + (size_t)(n0 + u) * (3 * CDIM) + 2 * CDIM + h * HSD;
            a += sc[u] * Vp[s];
        }
        part[g * HSD + s] = a;
    }
    __syncthreads();
    if (tid < HSD) {
        float a = part[tid] + part[HSD + tid] + part[2 * HSD + tid]
                + part[3 * HSD + tid] + part[4 * HSD + tid];
        att[(size_t)(n0 + t) * CDIM + h * HSD + tid] = a * inv;
    }
}

// ======================= gate softmax =======================
__global__ void gate_kernel(const float* __restrict__ h2,
                            const float* __restrict__ gw,
                            const float* __restrict__ gb,
                            float* __restrict__ gates) {
    int n = blockIdx.x;
    int e = threadIdx.x;
    const float* hr = h2 + (size_t)n * CDIM;
    float acc = gb[e];
    for (int c = 0; c < CDIM; c++) acc += hr[c] * gw[c * NE + e];
    float mx = acc;
    for (int o = 16; o > 0; o >>= 1) mx = fmaxf(mx, __shfl_xor_sync(0xFFFFFFFFu, mx, o));
    float ex = expf(acc - mx);
    float sm = ex;
    for (int o = 16; o > 0; o >>= 1) sm += __shfl_xor_sync(0xFFFFFFFFu, sm, o);
    gates[n * NE + e] = ex / sm;
}

// ======================= MoE combine =======================
__global__ void combine_kernel(const float* __restrict__ eo,
                               const float* __restrict__ gates,
                               float* __restrict__ x) {
    int n = blockIdx.x;
    __shared__ float gs[NE];
    if (threadIdx.x < NE) gs[threadIdx.x] = gates[n * NE + threadIdx.x];
    __syncthreads();
    for (int c = threadIdx.x; c < CDIM; c += blockDim.x) {
        float a = 0.f;
        const float* er = eo + (size_t)n * (NE * CDIM) + c;
#pragma unroll 8
        for (int e = 0; e < NE; e++) a += gs[e] * er[e * CDIM];
        x[(size_t)n * CDIM + c] += a;
    }
}

// ======================= launch =======================
extern "C" void kernel_launch(void* const* d_in, const int* in_sizes, int n_in,
                              void* d_out, int out_size) {
    const int*   idx    = (const int*)  d_in[0];
    const float* tok    = (const float*)d_in[1];
    const float* pos    = (const float*)d_in[2];
    const float* ln1_g  = (const float*)d_in[3];
    const float* ln1_b  = (const float*)d_in[4];
    const float* Wq     = (const float*)d_in[5];
    const float* Wk     = (const float*)d_in[6];
    const float* Wv     = (const float*)d_in[7];
    const float* Wo     = (const float*)d_in[8];
    const float* bo     = (const float*)d_in[9];
    const float* ln2_g  = (const float*)d_in[10];
    const float* ln2_b  = (const float*)d_in[11];
    const float* gate_w = (const float*)d_in[12];
    const float* gate_b = (const float*)d_in[13];
    const float* W1     = (const float*)d_in[14];
    const float* b1     = (const float*)d_in[15];
    const float* W2     = (const float*)d_in[16];
    const float* b2     = (const float*)d_in[17];
    const float* lnf_g  = (const float*)d_in[18];
    const float* lnf_b  = (const float*)d_in[19];
    const float* lm_w   = (const float*)d_in[20];
    const float* lm_b   = (const float*)d_in[21];
    float* out = (float*)d_out;

    float *x, *h, *qkv, *att, *wp, *gates, *hid, *eo;
    cudaGetSymbolAddress((void**)&x,     g_x);
    cudaGetSymbolAddress((void**)&h,     g_h);
    cudaGetSymbolAddress((void**)&qkv,   g_qkv);
    cudaGetSymbolAddress((void**)&att,   g_att);
    cudaGetSymbolAddress((void**)&wp,    g_wp);
    cudaGetSymbolAddress((void**)&gates, g_gates);
    cudaGetSymbolAddress((void**)&hid,   g_hid);
    cudaGetSymbolAddress((void**)&eo,    g_eo);

    cudaFuncSetAttribute(moe_mma<0>, cudaFuncAttributeMaxDynamicSharedMemorySize, MM_SMEM);
    cudaFuncSetAttribute(moe_mma<1>, cudaFuncAttributeMaxDynamicSharedMemorySize, MM_SMEM);
    cudaFuncSetAttribute(moe_mma<2>, cudaFuncAttributeMaxDynamicSharedMemorySize, MM_SMEM);
    cudaFuncSetAttribute(moe_mma<3>, cudaFuncAttributeMaxDynamicSharedMemorySize, MM_SMEM);

    const int MT = (NTOK + 127) / 128;   // 7

    embed_kernel<<<NTOK, 256>>>(idx, tok, pos, x);

    for (int l = 0; l < NL; l++) {
        // --- attention ---
        ln_kernel<<<NTOK, 256>>>(x, ln1_g + l * CDIM, ln1_b + l * CDIM, h);
        pack_qkv_kernel<<<(CDIM * CDIM + 255) / 256, 256>>>(
            Wq + (size_t)l * NH * CDIM * HSD,
            Wk + (size_t)l * NH * CDIM * HSD,
            Wv + (size_t)l * NH * CDIM * HSD, wp);
        // qkv = h @ wp  (N = 2304 = 18*128, K = 768 = 24*32)
        moe_mma<0><<<dim3(MT * 18, 1), 256, MM_SMEM>>>(
            h, CDIM, 0, wp, 0, 3 * CDIM, nullptr, 0,
            qkv, 3 * CDIM, 0, NTOK, 18, CDIM / 32);
        attn_kernel<<<dim3(TSEQ, NH, BSZ), 128>>>(qkv, att);
        // x += att @ Wo + bo  (N = 768 = 6*128)
        moe_mma<2><<<dim3(MT * 6, 1), 256, MM_SMEM>>>(
            att, CDIM, 0, Wo + (size_t)l * CDIM * CDIM, 0, CDIM,
            bo + l * CDIM, 0,
            x, CDIM, 0, NTOK, 6, CDIM / 32);

        // --- MoE ---
        ln_kernel<<<NTOK, 256>>>(x, ln2_g + l * CDIM, ln2_b + l * CDIM, h);
        gate_kernel<<<NTOK, 32>>>(h, gate_w + (size_t)l * CDIM * NE,
                                  gate_b + l * NE, gates);
        // up: hid[m, e*F4D + n] = gelu(h @ W1_e + b1_e)
        moe_mma<3><<<dim3(MT * (F4D / 128), NE), 256, MM_SMEM>>>(
            h, CDIM, 0,
            W1 + (size_t)l * NE * CDIM * F4D, (long long)CDIM * F4D, F4D,
            b1 + (size_t)l * NE * F4D, F4D,
            hid, (long long)NE * F4D, F4D,
            NTOK, F4D / 128, CDIM / 32);
        // down: eo[m, e*C + n] = hid_e @ W2_e + b2_e
        moe_mma<1><<<dim3(MT * (CDIM / 128), NE), 256, MM_SMEM>>>(
            hid, (long long)NE * F4D, F4D,
            W2 + (size_t)l * NE * F4D * CDIM, (long long)F4D * CDIM, CDIM,
            b2 + (size_t)l * NE * CDIM, CDIM,
            eo, (long long)NE * CDIM, CDIM,
            NTOK, CDIM / 128, F4D / 32);
        combine_kernel<<<NTOK, 256>>>(eo, gates, x);
    }

    // --- final LN + lm head (N=100, scalar) ---
    ln_kernel<<<NTOK, 256>>>(x, lnf_g, lnf_b, h);
    sgemm_kernel<1><<<dim3((NV + 63) / 64, (NTOK + 63) / 64), 256>>>(
        h, CDIM, lm_w, NV, lm_b,
        out, NV, NTOK, NV, CDIM);
}

// round 4
// speedup vs baseline: 2.5873x; 1.2386x over previous
#include <cuda_runtime.h>
#include <cuda_bf16.h>
#include <math.h>
#include <stdint.h>

// ---- problem constants ----
#define NTOK 844      // B*T = 2*422
#define TSEQ 422
#define BSZ  2
#define CDIM 768
#define NH   32
#define HSD  24
#define NE   32
#define F4D  3072
#define NL   2
#define NV   100

typedef __nv_bfloat16 bf16;
typedef __nv_bfloat162 bf162;

// ---- device scratch ----
__device__ float g_x  [NTOK * CDIM];
__device__ float g_h  [NTOK * CDIM];
__device__ float g_qkv[NTOK * 3 * CDIM];
__device__ float g_gates[NTOK * NE];
__device__ float g_eo [(size_t)NTOK * NE * CDIM];

__device__ bf16 g_hh [NTOK * CDIM],  g_hl [NTOK * CDIM];
__device__ bf16 g_atth[NTOK * CDIM], g_attl[NTOK * CDIM];
__device__ bf16 g_wpth[3 * CDIM * CDIM], g_wptl[3 * CDIM * CDIM];
__device__ bf16 g_woth[NL * CDIM * CDIM], g_wotl[NL * CDIM * CDIM];
__device__ bf16 g_w1th[(size_t)NL * NE * F4D * CDIM];
__device__ bf16 g_w1tl[(size_t)NL * NE * F4D * CDIM];
__device__ bf16 g_w2th[(size_t)NL * NE * CDIM * F4D];
__device__ bf16 g_w2tl[(size_t)NL * NE * CDIM * F4D];
__device__ bf16 g_hidh[(size_t)NTOK * NE * F4D];
__device__ bf16 g_hidl[(size_t)NTOK * NE * F4D];

// ======================= helpers =======================
__device__ __forceinline__ float gelu_exact(float v) {
    return 0.5f * v * (1.f + erff(v * 0.70710678118654752f));
}

__device__ __forceinline__ void mma16816(float* d, const unsigned* a, const unsigned* b) {
    asm volatile(
        "mma.sync.aligned.m16n8k16.row.col.f32.bf16.bf16.f32 "
        "{%0,%1,%2,%3}, {%4,%5,%6,%7}, {%8,%9}, {%0,%1,%2,%3};"
        : "+f"(d[0]), "+f"(d[1]), "+f"(d[2]), "+f"(d[3])
        : "r"(a[0]), "r"(a[1]), "r"(a[2]), "r"(a[3]), "r"(b[0]), "r"(b[1]));
}

__device__ __forceinline__ void cpa16(unsigned s, const void* g, int sz) {
    asm volatile("cp.async.cg.shared.global [%0], [%1], 16, %2;"
                 :: "r"(s), "l"(g), "r"(sz));
}
#define CPA_COMMIT() asm volatile("cp.async.commit_group;" ::: "memory")
#define CPA_WAIT(n)  asm volatile("cp.async.wait_group %0;" :: "n"(n) : "memory")

#define LDSM4(r0, r1, r2, r3, addr)                                            \
    asm volatile("ldmatrix.sync.aligned.m8n8.x4.shared.b16 {%0,%1,%2,%3}, [%4];" \
        : "=r"(r0), "=r"(r1), "=r"(r2), "=r"(r3) : "r"(addr))

// ======================= bf16x3 HMMA GEMM, preconverted operands ==============
// C_e[m, n] = epi( sum_k A_e[m,k] * B_e[n,k] ); A,B stored as bf16 hi/lo planes.
// B transposed: [n][k] row-major. 128x128 tile per CTA, 8 warps (64x32 each).
// EP: 0 -> Cf plain; 1 -> Cf +bias; 2 -> Cf += (+bias); 3 -> gelu(+bias) -> Ch/Cl.
#define STR 40                     // smem row stride (elems); rows 80B
#define PLANE_B (128 * 80)         // 10240
#define STAGE_B (4 * PLANE_B)      // 40960
#define MM_SMEM (2 * STAGE_B)      // 81920

template <int EP>
__global__ void __launch_bounds__(256, 2)
mma_gemm(const bf16* __restrict__ Ah, const bf16* __restrict__ Al,
         long long lda, long long aExp,
         const bf16* __restrict__ Bh, const bf16* __restrict__ Bl,
         long long ldb, long long bExp,
         const float* __restrict__ bias, long long biasExp,
         float* __restrict__ Cf, bf16* __restrict__ Ch, bf16* __restrict__ Cl,
         long long ldc, long long cExp,
         int M, int Ntiles, int KC) {
    extern __shared__ char smc[];
    unsigned smbase;
    asm("{ .reg .u64 t; cvta.to.shared.u64 t, %1; cvt.u32.u64 %0, t; }"
        : "=r"(smbase) : "l"(smc));

    const int tid = threadIdx.x, wid = tid >> 5, lane = tid & 31;
    const int g = lane >> 2, tg = lane & 3;
    const int wm = wid >> 2, wn = wid & 3;
    const int e = blockIdx.y;
    const int nt = blockIdx.x % Ntiles, mt = blockIdx.x / Ntiles;
    const int n0 = nt * 128, m0 = mt * 128;

    const bf16* Abh = Ah + (size_t)e * aExp;
    const bf16* Abl = Al + (size_t)e * aExp;
    const bf16* Bbh = Bh + (size_t)e * bExp;
    const bf16* Bbl = Bl + (size_t)e * bExp;

    // ldmatrix lane address components
    const int s4 = lane >> 3, lr = lane & 7;
    const int aRowL = lr + (s4 & 1) * 8, aColL = (s4 >> 1) * 8;
    const int bRowL = lr + (s4 >> 1) * 8, bColL = (s4 & 1) * 8;

    float acc[4][4][4];
#pragma unroll
    for (int i = 0; i < 4; i++)
#pragma unroll
        for (int j = 0; j < 4; j++)
#pragma unroll
            for (int r = 0; r < 4; r++) acc[i][j][r] = 0.f;

    const int fRow = tid >> 2, fCh = tid & 3;   // fill: row 0..63 (+64), chunk 0..3

    auto issue = [&](int c) {
        const int k0 = c * 32;
        unsigned sb = smbase + (c & 1) * STAGE_B;
#pragma unroll
        for (int i = 0; i < 2; i++) {
            int row = fRow + i * 64;
            int m = m0 + row;
            int sz = (m < M) ? 16 : 0;
            size_t go = (size_t)(m < M ? m : 0) * lda + k0 + fCh * 8;
            unsigned so = sb + row * 80 + fCh * 16;
            cpa16(so, Abh + go, sz);
            cpa16(so + PLANE_B, Abl + go, sz);
        }
#pragma unroll
        for (int i = 0; i < 2; i++) {
            int row = fRow + i * 64;
            size_t go = (size_t)(n0 + row) * ldb + k0 + fCh * 8;
            unsigned so = sb + 2 * PLANE_B + row * 80 + fCh * 16;
            cpa16(so, Bbh + go, 16);
            cpa16(so + PLANE_B, Bbl + go, 16);
        }
    };

    issue(0);
    CPA_COMMIT();

    for (int c = 0; c < KC; ++c) {
        if (c + 1 < KC) { issue(c + 1); CPA_COMMIT(); CPA_WAIT(1); }
        else            { CPA_WAIT(0); }
        __syncthreads();

        unsigned sb = smbase + (c & 1) * STAGE_B;
#pragma unroll
        for (int ks = 0; ks < 2; ks++) {
            const int kb = ks * 16;
            unsigned bh_[4][2], bl_[4][2];
#pragma unroll
            for (int p = 0; p < 2; p++) {
                int rn0 = wn * 32 + p * 16;
                unsigned ba = sb + 2 * PLANE_B +
                              (unsigned)((rn0 + bRowL) * STR + kb + bColL) * 2;
                LDSM4(bh_[2 * p][0], bh_[2 * p][1], bh_[2 * p + 1][0], bh_[2 * p + 1][1], ba);
                LDSM4(bl_[2 * p][0], bl_[2 * p][1], bl_[2 * p + 1][0], bl_[2 * p + 1][1],
                      ba + PLANE_B);
            }
#pragma unroll
            for (int mi = 0; mi < 4; mi++) {
                int rm0 = wm * 64 + mi * 16;
                unsigned aa = sb + (unsigned)((rm0 + aRowL) * STR + kb + aColL) * 2;
                unsigned ah_[4], al_[4];
                LDSM4(ah_[0], ah_[1], ah_[2], ah_[3], aa);
                LDSM4(al_[0], al_[1], al_[2], al_[3], aa + PLANE_B);
#pragma unroll
                for (int ni = 0; ni < 4; ni++) {
                    mma16816(acc[mi][ni], ah_, bh_[ni]);
                    mma16816(acc[mi][ni], ah_, bl_[ni]);
                    mma16816(acc[mi][ni], al_, bh_[ni]);
                }
            }
        }
        __syncthreads();
    }

    // ---- epilogue ----
#pragma unroll
    for (int mi = 0; mi < 4; mi++) {
        int r0 = m0 + wm * 64 + mi * 16 + g;
#pragma unroll
        for (int ni = 0; ni < 4; ni++) {
            int j = wn * 32 + ni * 8 + tg * 2;
            float b0 = 0.f, b1 = 0.f;
            if (EP >= 1) {
                b0 = bias[(size_t)e * biasExp + n0 + j];
                b1 = bias[(size_t)e * biasExp + n0 + j + 1];
            }
#pragma unroll
            for (int hh = 0; hh < 2; hh++) {
                int r = r0 + hh * 8;
                if (r >= M) continue;
                float v0 = acc[mi][ni][hh * 2 + 0] + b0;
                float v1 = acc[mi][ni][hh * 2 + 1] + b1;
                size_t o = (size_t)e * cExp + (size_t)r * ldc + n0 + j;
                if (EP == 3) {
                    v0 = gelu_exact(v0); v1 = gelu_exact(v1);
                    bf16 h0 = __float2bfloat16_rn(v0), h1 = __float2bfloat16_rn(v1);
                    bf162 hv; hv.x = h0; hv.y = h1;
                    bf162 lv;
                    lv.x = __float2bfloat16_rn(v0 - __bfloat162float(h0));
                    lv.y = __float2bfloat16_rn(v1 - __bfloat162float(h1));
                    *(bf162*)(Ch + o) = hv;
                    *(bf162*)(Cl + o) = lv;
                } else if (EP == 2) {
                    Cf[o] += v0; Cf[o + 1] += v1;
                } else {
                    *(float2*)(Cf + o) = make_float2(v0, v1);
                }
            }
        }
    }
}

// ======================= transpose + split convert =======================
// src: per-expert [K][N] fp32 -> th/tl: per-expert [N][K] bf16
__global__ void convT(const float* __restrict__ src, long long sExp, int K, int N,
                      bf16* __restrict__ th, bf16* __restrict__ tl, long long tExp) {
    __shared__ float t[32][33];
    int e = blockIdx.z;
    int k0 = blockIdx.x * 32, nn0 = blockIdx.y * 32;
    int tx = threadIdx.x, ty = threadIdx.y;   // 32 x 8
    const float* sp = src + (size_t)e * sExp;
#pragma unroll
    for (int r = 0; r < 4; r++) {
        int k = k0 + ty + r * 8;
        t[ty + r * 8][tx] = sp[(size_t)k * N + nn0 + tx];
    }
    __syncthreads();
#pragma unroll
    for (int r = 0; r < 4; r++) {
        int n = nn0 + ty + r * 8;
        float v = t[tx][ty + r * 8];
        bf16 hi = __float2bfloat16_rn(v);
        size_t o = (size_t)e * tExp + (size_t)n * K + k0 + tx;
        th[o] = hi;
        tl[o] = __float2bfloat16_rn(v - __bfloat162float(hi));
    }
}

// ======================= pack Wq/Wk/Wv -> transposed bf16 planes [3C][C] ======
__global__ void pack_qkvT(const float* __restrict__ Wq,
                          const float* __restrict__ Wk,
                          const float* __restrict__ Wv,
                          bf16* __restrict__ th, bf16* __restrict__ tl) {
    int j = blockIdx.x;                        // 0..3*C-1
    int which = j / CDIM, hs = j % CDIM;
    int h = hs / HSD, s = hs % HSD;
    const float* W = (which == 0) ? Wq : ((which == 1) ? Wk : Wv);
    for (int c = threadIdx.x; c < CDIM; c += 256) {
        float v = W[((size_t)h * CDIM + c) * HSD + s];
        bf16 hi = __float2bfloat16_rn(v);
        size_t o = (size_t)j * CDIM + c;
        th[o] = hi;
        tl[o] = __float2bfloat16_rn(v - __bfloat162float(hi));
    }
}

// ======================= embedding =======================
__global__ void embed_kernel(const int* __restrict__ idx,
                             const float* __restrict__ tok,
                             const float* __restrict__ pos,
                             float* __restrict__ x) {
    int n = blockIdx.x;
    int t = n % TSEQ;
    int v = idx[n];
    for (int c = threadIdx.x; c < CDIM; c += blockDim.x)
        x[n * CDIM + c] = tok[v * CDIM + c] + pos[t * CDIM + c];
}

// ======================= layernorm (fp32 + bf16 hi/lo planes) ==============
__global__ void ln_kernel(const float* __restrict__ x,
                          const float* __restrict__ g,
                          const float* __restrict__ b,
                          float* __restrict__ out,
                          bf16* __restrict__ oh, bf16* __restrict__ ol) {
    int n = blockIdx.x;
    int tid = threadIdx.x;
    __shared__ float s1[256], s2[256];
    const float* xr = x + (size_t)n * CDIM;
    float a = 0.f, q = 0.f;
    for (int c = tid; c < CDIM; c += 256) { float v = xr[c]; a += v; q += v * v; }
    s1[tid] = a; s2[tid] = q;
    __syncthreads();
    for (int s = 128; s > 0; s >>= 1) {
        if (tid < s) { s1[tid] += s1[tid + s]; s2[tid] += s2[tid + s]; }
        __syncthreads();
    }
    float mean = s1[0] * (1.f / CDIM);
    float var  = s2[0] * (1.f / CDIM) - mean * mean;
    float r = rsqrtf(var + 1e-5f);
    for (int c = tid; c < CDIM; c += 256) {
        float o = (xr[c] - mean) * r * g[c] + b[c];
        size_t p = (size_t)n * CDIM + c;
        out[p] = o;
        bf16 hi = __float2bfloat16_rn(o);
        oh[p] = hi;
        ol[p] = __float2bfloat16_rn(o - __bfloat162float(hi));
    }
}

// ======================= attention =======================
__global__ void attn_kernel(const float* __restrict__ qkv,
                            bf16* __restrict__ atth, bf16* __restrict__ attl) {
    int t = blockIdx.x, h = blockIdx.y, b = blockIdx.z;
    int tid = threadIdx.x;
    __shared__ float sc[TSEQ];
    __shared__ float qs[HSD];
    __shared__ float red[128];
    __shared__ float part[5 * HSD];

    int n0 = b * TSEQ;
    const float* Q = qkv + (size_t)(n0 + t) * (3 * CDIM) + h * HSD;
    if (tid < HSD) qs[tid] = Q[tid];
    __syncthreads();

    const float scale = 0.20412414523193154f;
    float lmax = -1e30f;
    for (int u = tid; u <= t; u += 128) {
        const float* Kp = qkv + (size_t)(n0 + u) * (3 * CDIM) + CDIM + h * HSD;
        float d = 0.f;
#pragma unroll
        for (int s = 0; s < HSD; s++) d += qs[s] * Kp[s];
        d *= scale;
        sc[u] = d;
        lmax = fmaxf(lmax, d);
    }
    red[tid] = lmax;
    __syncthreads();
    for (int s = 64; s > 0; s >>= 1) {
        if (tid < s) red[tid] = fmaxf(red[tid], red[tid + s]);
        __syncthreads();
    }
    float mx = red[0];
    __syncthreads();

    float lsum = 0.f;
    for (int u = tid; u <= t; u += 128) {
        float ev = expf(sc[u] - mx);
        sc[u] = ev;
        lsum += ev;
    }
    red[tid] = lsum;
    __syncthreads();
    for (int s = 64; s > 0; s >>= 1) {
        if (tid < s) red[tid] += red[tid + s];
        __syncthreads();
    }
    float inv = 1.f / red[0];
    __syncthreads();

    if (tid < 120) {
        int s = tid % HSD, gg = tid / HSD;
        float a = 0.f;
        for (int u = gg; u <= t; u += 5) {
            const float* Vp = qkv + (size_t)(n0 + u) * (3 * CDIM) + 2 * CDIM + h * HSD;
            a += sc[u] * Vp[s];
        }
        part[gg * HSD + s] = a;
    }
    __syncthreads();
    if (tid < HSD) {
        float a = (part[tid] + part[HSD + tid] + part[2 * HSD + tid]
                 + part[3 * HSD + tid] + part[4 * HSD + tid]) * inv;
        size_t o = (size_t)(n0 + t) * CDIM + h * HSD + tid;
        bf16 hi = __float2bfloat16_rn(a);
        atth[o] = hi;
        attl[o] = __float2bfloat16_rn(a - __bfloat162float(hi));
    }
}

// ======================= gate softmax =======================
__global__ void gate_kernel(const float* __restrict__ h2,
                            const float* __restrict__ gw,
                            const float* __restrict__ gb,
                            float* __restrict__ gates) {
    int n = blockIdx.x;
    int e = threadIdx.x;
    const float* hr = h2 + (size_t)n * CDIM;
    float acc = gb[e];
    for (int c = 0; c < CDIM; c++) acc += hr[c] * gw[c * NE + e];
    float mx = acc;
    for (int o = 16; o > 0; o >>= 1) mx = fmaxf(mx, __shfl_xor_sync(0xFFFFFFFFu, mx, o));
    float ex = expf(acc - mx);
    float sm = ex;
    for (int o = 16; o > 0; o >>= 1) sm += __shfl_xor_sync(0xFFFFFFFFu, sm, o);
    gates[n * NE + e] = ex / sm;
}

// ======================= MoE combine =======================
__global__ void combine_kernel(const float* __restrict__ eo,
                               const float* __restrict__ gates,
                               float* __restrict__ x) {
    int n = blockIdx.x;
    __shared__ float gs[NE];
    if (threadIdx.x < NE) gs[threadIdx.x] = gates[n * NE + threadIdx.x];
    __syncthreads();
    for (int c = threadIdx.x; c < CDIM; c += blockDim.x) {
        float a = 0.f;
        const float* er = eo + (size_t)n * (NE * CDIM) + c;
#pragma unroll 8
        for (int e = 0; e < NE; e++) a += gs[e] * er[e * CDIM];
        x[(size_t)n * CDIM + c] += a;
    }
}

// ======================= scalar SGEMM (lm head only) =======================
__global__ void __launch_bounds__(256)
lm_head_kernel(const float* __restrict__ A, const float* __restrict__ B,
               const float* __restrict__ bias, float* __restrict__ C,
               int M, int N, int K) {
    __shared__ float As[64][17];
    __shared__ float Bs[16][64];
    int tid = threadIdx.x;
    int jTile = blockIdx.x * 64;
    int mTile = blockIdx.y * 64;
    int tx = tid & 15, ty = tid >> 4;

    float acc[4][4];
#pragma unroll
    for (int r = 0; r < 4; r++)
#pragma unroll
        for (int c = 0; c < 4; c++) acc[r][c] = 0.f;

    int aRow = tid >> 2, aK = (tid & 3) * 4;
    int bJ = tid & 63, bK0 = tid >> 6;

    for (int k0 = 0; k0 < K; k0 += 16) {
        int m = mTile + aRow;
        if (m < M) {
            float4 av = *(const float4*)(A + (size_t)m * K + k0 + aK);
            As[aRow][aK + 0] = av.x; As[aRow][aK + 1] = av.y;
            As[aRow][aK + 2] = av.z; As[aRow][aK + 3] = av.w;
        } else {
            As[aRow][aK + 0] = 0.f; As[aRow][aK + 1] = 0.f;
            As[aRow][aK + 2] = 0.f; As[aRow][aK + 3] = 0.f;
        }
#pragma unroll
        for (int i = 0; i < 4; i++) {
            int kk = bK0 + i * 4;
            Bs[kk][bJ] = (jTile + bJ < N)
                ? B[(size_t)(k0 + kk) * N + jTile + bJ] : 0.f;
        }
        __syncthreads();
#pragma unroll
        for (int k = 0; k < 16; k++) {
            float4 bv = *(const float4*)&Bs[k][tx * 4];
            float a0 = As[ty * 4 + 0][k], a1 = As[ty * 4 + 1][k];
            float a2 = As[ty * 4 + 2][k], a3 = As[ty * 4 + 3][k];
            acc[0][0] += a0 * bv.x; acc[0][1] += a0 * bv.y; acc[0][2] += a0 * bv.z; acc[0][3] += a0 * bv.w;
            acc[1][0] += a1 * bv.x; acc[1][1] += a1 * bv.y; acc[1][2] += a1 * bv.z; acc[1][3] += a1 * bv.w;
            acc[2][0] += a2 * bv.x; acc[2][1] += a2 * bv.y; acc[2][2] += a2 * bv.z; acc[2][3] += a2 * bv.w;
            acc[3][0] += a3 * bv.x; acc[3][1] += a3 * bv.y; acc[3][2] += a3 * bv.z; acc[3][3] += a3 * bv.w;
        }
        __syncthreads();
    }
#pragma unroll
    for (int r = 0; r < 4; r++) {
        int m = mTile + ty * 4 + r;
        if (m >= M) continue;
#pragma unroll
        for (int c = 0; c < 4; c++) {
            int j = jTile + tx * 4 + c;
            if (j >= N) continue;
            C[(size_t)m * N + j] = acc[r][c] + bias[j];
        }
    }
}

// ======================= launch =======================
extern "C" void kernel_launch(void* const* d_in, const int* in_sizes, int n_in,
                              void* d_out, int out_size) {
    const int*   idx    = (const int*)  d_in[0];
    const float* tok    = (const float*)d_in[1];
    const float* pos    = (const float*)d_in[2];
    const float* ln1_g  = (const float*)d_in[3];
    const float* ln1_b  = (const float*)d_in[4];
    const float* Wq     = (const float*)d_in[5];
    const float* Wk     = (const float*)d_in[6];
    const float* Wv     = (const float*)d_in[7];
    const float* Wo     = (const float*)d_in[8];
    const float* bo     = (const float*)d_in[9];
    const float* ln2_g  = (const float*)d_in[10];
    const float* ln2_b  = (const float*)d_in[11];
    const float* gate_w = (const float*)d_in[12];
    const float* gate_b = (const float*)d_in[13];
    const float* W1     = (const float*)d_in[14];
    const float* b1     = (const float*)d_in[15];
    const float* W2     = (const float*)d_in[16];
    const float* b2     = (const float*)d_in[17];
    const float* lnf_g  = (const float*)d_in[18];
    const float* lnf_b  = (const float*)d_in[19];
    const float* lm_w   = (const float*)d_in[20];
    const float* lm_b   = (const float*)d_in[21];
    float* out = (float*)d_out;

    float *x, *h, *qkv, *gates, *eo;
    bf16 *hh, *hl, *atth, *attl, *wpth, *wptl, *woth, *wotl;
    bf16 *w1th, *w1tl, *w2th, *w2tl, *hidh, *hidl;
    cudaGetSymbolAddress((void**)&x,     g_x);
    cudaGetSymbolAddress((void**)&h,     g_h);
    cudaGetSymbolAddress((void**)&qkv,   g_qkv);
    cudaGetSymbolAddress((void**)&gates, g_gates);
    cudaGetSymbolAddress((void**)&eo,    g_eo);
    cudaGetSymbolAddress((void**)&hh,    g_hh);
    cudaGetSymbolAddress((void**)&hl,    g_hl);
    cudaGetSymbolAddress((void**)&atth,  g_atth);
    cudaGetSymbolAddress((void**)&attl,  g_attl);
    cudaGetSymbolAddress((void**)&wpth,  g_wpth);
    cudaGetSymbolAddress((void**)&wptl,  g_wptl);
    cudaGetSymbolAddress((void**)&woth,  g_woth);
    cudaGetSymbolAddress((void**)&wotl,  g_wotl);
    cudaGetSymbolAddress((void**)&w1th,  g_w1th);
    cudaGetSymbolAddress((void**)&w1tl,  g_w1tl);
    cudaGetSymbolAddress((void**)&w2th,  g_w2th);
    cudaGetSymbolAddress((void**)&w2tl,  g_w2tl);
    cudaGetSymbolAddress((void**)&hidh,  g_hidh);
    cudaGetSymbolAddress((void**)&hidl,  g_hidl);

    cudaFuncSetAttribute(mma_gemm<0>, cudaFuncAttributeMaxDynamicSharedMemorySize, MM_SMEM);
    cudaFuncSetAttribute(mma_gemm<1>, cudaFuncAttributeMaxDynamicSharedMemorySize, MM_SMEM);
    cudaFuncSetAttribute(mma_gemm<2>, cudaFuncAttributeMaxDynamicSharedMemorySize, MM_SMEM);
    cudaFuncSetAttribute(mma_gemm<3>, cudaFuncAttributeMaxDynamicSharedMemorySize, MM_SMEM);

    const int MT = (NTOK + 127) / 128;   // 7
    dim3 cblk(32, 8);

    // ---- pre-convert all weights (transpose + bf16 hi/lo split) ----
    for (int l = 0; l < NL; l++) {
        convT<<<dim3(CDIM / 32, F4D / 32, NE), cblk>>>(
            W1 + (size_t)l * NE * CDIM * F4D, (long long)CDIM * F4D, CDIM, F4D,
            w1th + (size_t)l * NE * F4D * CDIM, w1tl + (size_t)l * NE * F4D * CDIM,
            (long long)F4D * CDIM);
        convT<<<dim3(F4D / 32, CDIM / 32, NE), cblk>>>(
            W2 + (size_t)l * NE * F4D * CDIM, (long long)F4D * CDIM, F4D, CDIM,
            w2th + (size_t)l * NE * CDIM * F4D, w2tl + (size_t)l * NE * CDIM * F4D,
            (long long)CDIM * F4D);
        convT<<<dim3(CDIM / 32, CDIM / 32, 1), cblk>>>(
            Wo + (size_t)l * CDIM * CDIM, 0, CDIM, CDIM,
            woth + (size_t)l * CDIM * CDIM, wotl + (size_t)l * CDIM * CDIM, 0);
    }

    embed_kernel<<<NTOK, 256>>>(idx, tok, pos, x);

    for (int l = 0; l < NL; l++) {
        // --- attention ---
        ln_kernel<<<NTOK, 256>>>(x, ln1_g + l * CDIM, ln1_b + l * CDIM, h, hh, hl);
        pack_qkvT<<<3 * CDIM, 256>>>(
            Wq + (size_t)l * NH * CDIM * HSD,
            Wk + (size_t)l * NH * CDIM * HSD,
            Wv + (size_t)l * NH * CDIM * HSD, wpth, wptl);
        mma_gemm<0><<<dim3(MT * 18, 1), 256, MM_SMEM>>>(
            hh, hl, CDIM, 0, wpth, wptl, CDIM, 0,
            nullptr, 0, qkv, nullptr, nullptr, 3 * CDIM, 0,
            NTOK, 18, CDIM / 32);
        attn_kernel<<<dim3(TSEQ, NH, BSZ), 128>>>(qkv, atth, attl);
        mma_gemm<2><<<dim3(MT * 6, 1), 256, MM_SMEM>>>(
            atth, attl, CDIM, 0,
            woth + (size_t)l * CDIM * CDIM, wotl + (size_t)l * CDIM * CDIM, CDIM, 0,
            bo + l * CDIM, 0, x, nullptr, nullptr, CDIM, 0,
            NTOK, 6, CDIM / 32);

        // --- MoE ---
        ln_kernel<<<NTOK, 256>>>(x, ln2_g + l * CDIM, ln2_b + l * CDIM, h, hh, hl);
        gate_kernel<<<NTOK, 32>>>(h, gate_w + (size_t)l * CDIM * NE,
                                  gate_b + l * NE, gates);
        // up: hid = gelu(h @ W1_e + b1_e) -> bf16 hi/lo planes
        mma_gemm<3><<<dim3(MT * (F4D / 128), NE), 256, MM_SMEM>>>(
            hh, hl, CDIM, 0,
            w1th + (size_t)l * NE * F4D * CDIM, w1tl + (size_t)l * NE * F4D * CDIM,
            CDIM, (long long)F4D * CDIM,
            b1 + (size_t)l * NE * F4D, F4D,
            nullptr, hidh, hidl, (long long)NE * F4D, F4D,
            NTOK, F4D / 128, CDIM / 32);
        // down: eo = hid_e @ W2_e + b2_e
        mma_gemm<1><<<dim3(MT * (CDIM / 128), NE), 256, MM_SMEM>>>(
            hidh, hidl, (long long)NE * F4D, F4D,
            w2th + (size_t)l * NE * CDIM * F4D, w2tl + (size_t)l * NE * CDIM * F4D,
            F4D, (long long)CDIM * F4D,
            b2 + (size_t)l * NE * CDIM, CDIM,
            eo, nullptr, nullptr, (long long)NE * CDIM, CDIM,
            NTOK, CDIM / 128, F4D / 32);
        combine_kernel<<<NTOK, 256>>>(eo, gates, x);
    }

    // --- final LN + lm head ---
    ln_kernel<<<NTOK, 256>>>(x, lnf_g, lnf_b, h, hh, hl);
    lm_head_kernel<<<dim3((NV + 63) / 64, (NTOK + 63) / 64), 256>>>(
        h, lm_w, lm_b, out, NTOK, NV, CDIM);
}

// round 6
// speedup vs baseline: 3.2974x; 1.2745x over previous
#include <cuda_runtime.h>
#include <cuda_fp16.h>
#include <math.h>
#include <stdint.h>

// ---- problem constants ----
#define NTOK 844      // B*T = 2*422
#define TSEQ 422
#define BSZ  2
#define CDIM 768
#define NH   32
#define HSD  24
#define NE   32
#define F4D  3072
#define NL   2
#define NV   100

typedef __half fp16;

// ---- device scratch ----
__device__ float g_x  [NTOK * CDIM];
__device__ float g_h  [NTOK * CDIM];
__device__ float g_qkv[NTOK * 3 * CDIM];
__device__ float g_gates[NTOK * NE];
__device__ float g_eo [(size_t)NTOK * NE * CDIM];

__device__ fp16 g_hh [NTOK * CDIM],  g_hl [NTOK * CDIM];
__device__ fp16 g_atth[NTOK * CDIM], g_attl[NTOK * CDIM];
__device__ fp16 g_wpth[3 * CDIM * CDIM], g_wptl[3 * CDIM * CDIM];
__device__ fp16 g_woth[NL * CDIM * CDIM], g_wotl[NL * CDIM * CDIM];
__device__ fp16 g_w1th[(size_t)NL * NE * F4D * CDIM];
__device__ fp16 g_w1tl[(size_t)NL * NE * F4D * CDIM];
__device__ fp16 g_w2th[(size_t)NL * NE * CDIM * F4D];
__device__ fp16 g_w2tl[(size_t)NL * NE * CDIM * F4D];
__device__ fp16 g_hidh[(size_t)NTOK * NE * F4D];

// ======================= helpers =======================
__device__ __forceinline__ float gelu_exact(float v) {
    return 0.5f * v * (1.f + erff(v * 0.70710678118654752f));
}

__device__ __forceinline__ void mma16816(float* d, const unsigned* a, const unsigned* b) {
    asm volatile(
        "mma.sync.aligned.m16n8k16.row.col.f32.f16.f16.f32 "
        "{%0,%1,%2,%3}, {%4,%5,%6,%7}, {%8,%9}, {%0,%1,%2,%3};"
        : "+f"(d[0]), "+f"(d[1]), "+f"(d[2]), "+f"(d[3])
        : "r"(a[0]), "r"(a[1]), "r"(a[2]), "r"(a[3]), "r"(b[0]), "r"(b[1]));
}

__device__ __forceinline__ void cpa16(unsigned s, const void* g, int sz) {
    asm volatile("cp.async.cg.shared.global [%0], [%1], 16, %2;"
                 :: "r"(s), "l"(g), "r"(sz));
}
#define CPA_COMMIT() asm volatile("cp.async.commit_group;" ::: "memory")
#define CPA_WAIT(n)  asm volatile("cp.async.wait_group %0;" :: "n"(n) : "memory")

#define LDSM4(r0, r1, r2, r3, addr)                                            \
    asm volatile("ldmatrix.sync.aligned.m8n8.x4.shared.b16 {%0,%1,%2,%3}, [%4];" \
        : "=r"(r0), "=r"(r1), "=r"(r2), "=r"(r3) : "r"(addr))

// ======================= fp16 split HMMA GEMM =======================
// C_e[m,n] = epi( sum_k A_e[m,k]*B_e[n,k] ); operands pre-split fp16 hi/lo planes.
// NT=3: AhBh + AhBl + AlBh (err ~2^-22).  NT=2: AhBh + AhBl (err ~2^-12), no A-lo.
// 128x128 tile/CTA, 8 warps (64x32). EP: 0 Cf; 1 Cf+bias; 2 Cf += (+bias);
// 3 gelu(+bias) -> Ch (fp16 hi only).
#define STR 40                     // smem row stride (elems); 80B rows
#define PLANE_B (128 * 80)         // 10240
#define EPI_BYTES (128 * 132 * 4)  // 67584
#define SMEM_NT3 81920             // 2 stages * 4 planes
#define SMEM_NT2 69632             // max(2*3 planes=61440, EPI) rounded up

template <int EP, int NT>
__global__ void __launch_bounds__(256, 2)
mma_gemm(const fp16* __restrict__ Ah, const fp16* __restrict__ Al,
         long long lda, long long aExp,
         const fp16* __restrict__ Bh, const fp16* __restrict__ Bl,
         long long ldb, long long bExp,
         const float* __restrict__ bias, long long biasExp,
         float* __restrict__ Cf, fp16* __restrict__ Ch,
         long long ldc, long long cExp,
         int M, int Ntiles, int KC) {
    constexpr int APL = (NT == 3) ? 2 : 1;
    constexpr unsigned STAGE_B = (APL + 2) * PLANE_B;
    extern __shared__ char smc[];
    unsigned smbase;
    asm("{ .reg .u64 t; cvta.to.shared.u64 t, %1; cvt.u32.u64 %0, t; }"
        : "=r"(smbase) : "l"(smc));

    const int tid = threadIdx.x, wid = tid >> 5, lane = tid & 31;
    const int g = lane >> 2, tg = lane & 3;
    const int wm = wid >> 2, wn = wid & 3;
    const int e = blockIdx.y;
    const int nt = blockIdx.x % Ntiles, mt = blockIdx.x / Ntiles;
    const int n0 = nt * 128, m0 = mt * 128;

    const fp16* Abh = Ah + (size_t)e * aExp;
    const fp16* Abl = (NT == 3) ? (Al + (size_t)e * aExp) : nullptr;
    const fp16* Bbh = Bh + (size_t)e * bExp;
    const fp16* Bbl = Bl + (size_t)e * bExp;

    const int s4 = lane >> 3, lr = lane & 7;
    const int aRowL = lr + (s4 & 1) * 8, aColL = (s4 >> 1) * 8;
    const int bRowL = lr + (s4 >> 1) * 8, bColL = (s4 & 1) * 8;

    float acc[4][4][4];
#pragma unroll
    for (int i = 0; i < 4; i++)
#pragma unroll
        for (int j = 0; j < 4; j++)
#pragma unroll
            for (int r = 0; r < 4; r++) acc[i][j][r] = 0.f;

    const int fRow = tid >> 2, fCh = tid & 3;

    auto issue = [&](int c) {
        const int k0 = c * 32;
        unsigned sb = smbase + (c & 1) * STAGE_B;
#pragma unroll
        for (int i = 0; i < 2; i++) {
            int row = fRow + i * 64;
            int m = m0 + row;
            int sz = (m < M) ? 16 : 0;
            size_t go = (size_t)(m < M ? m : 0) * lda + k0 + fCh * 8;
            unsigned so = sb + row * 80 + fCh * 16;
            cpa16(so, Abh + go, sz);
            if (NT == 3) cpa16(so + PLANE_B, Abl + go, sz);
        }
#pragma unroll
        for (int i = 0; i < 2; i++) {
            int row = fRow + i * 64;
            size_t go = (size_t)(n0 + row) * ldb + k0 + fCh * 8;
            unsigned so = sb + APL * PLANE_B + row * 80 + fCh * 16;
            cpa16(so, Bbh + go, 16);
            cpa16(so + PLANE_B, Bbl + go, 16);
        }
    };

    issue(0);
    CPA_COMMIT();

    for (int c = 0; c < KC; ++c) {
        if (c + 1 < KC) { issue(c + 1); CPA_COMMIT(); CPA_WAIT(1); }
        else            { CPA_WAIT(0); }
        __syncthreads();

        unsigned sb = smbase + (c & 1) * STAGE_B;
#pragma unroll
        for (int ks = 0; ks < 2; ks++) {
            const int kb = ks * 16;
            unsigned bh_[4][2], bl_[4][2];
#pragma unroll
            for (int p = 0; p < 2; p++) {
                int rn0 = wn * 32 + p * 16;
                unsigned ba = sb + APL * PLANE_B +
                              (unsigned)((rn0 + bRowL) * STR + kb + bColL) * 2;
                LDSM4(bh_[2 * p][0], bh_[2 * p][1], bh_[2 * p + 1][0], bh_[2 * p + 1][1], ba);
                LDSM4(bl_[2 * p][0], bl_[2 * p][1], bl_[2 * p + 1][0], bl_[2 * p + 1][1],
                      ba + PLANE_B);
            }
#pragma unroll
            for (int mi = 0; mi < 4; mi++) {
                int rm0 = wm * 64 + mi * 16;
                unsigned aa = sb + (unsigned)((rm0 + aRowL) * STR + kb + aColL) * 2;
                unsigned ah_[4], al_[4];
                LDSM4(ah_[0], ah_[1], ah_[2], ah_[3], aa);
                if (NT == 3) LDSM4(al_[0], al_[1], al_[2], al_[3], aa + PLANE_B);
#pragma unroll
                for (int ni = 0; ni < 4; ni++) {
                    mma16816(acc[mi][ni], ah_, bh_[ni]);
                    mma16816(acc[mi][ni], ah_, bl_[ni]);
                    if (NT == 3) mma16816(acc[mi][ni], al_, bh_[ni]);
                }
            }
        }
        __syncthreads();
    }

    // ---- epilogue: regs -> smem (fp32, stride 132) -> coalesced gmem ----
    float* sOut = (float*)smc;
#pragma unroll
    for (int mi = 0; mi < 4; mi++) {
        int lrow = wm * 64 + mi * 16 + g;
#pragma unroll
        for (int ni = 0; ni < 4; ni++) {
            int j = wn * 32 + ni * 8 + tg * 2;
            float b0 = 0.f, b1 = 0.f;
            if (EP >= 1) {
                b0 = bias[(size_t)e * biasExp + n0 + j];
                b1 = bias[(size_t)e * biasExp + n0 + j + 1];
            }
#pragma unroll
            for (int hh = 0; hh < 2; hh++) {
                float v0 = acc[mi][ni][hh * 2 + 0] + b0;
                float v1 = acc[mi][ni][hh * 2 + 1] + b1;
                if (EP == 3) { v0 = gelu_exact(v0); v1 = gelu_exact(v1); }
                float2 o2 = make_float2(v0, v1);
                *(float2*)&sOut[(lrow + hh * 8) * 132 + j] = o2;
            }
        }
    }
    __syncthreads();

    if (EP == 3) {
        // write fp16 hi plane, coalesced 16B stores
#pragma unroll
        for (int i = 0; i < 8; i++) {
            int item = tid + i * 256;
            int row = item >> 4;
            int c8 = (item & 15) * 8;
            int m = m0 + row;
            if (m >= M) continue;
            float4 f0 = *(float4*)&sOut[row * 132 + c8];
            float4 f1 = *(float4*)&sOut[row * 132 + c8 + 4];
            __half2 h0 = __floats2half2_rn(f0.x, f0.y);
            __half2 h1 = __floats2half2_rn(f0.z, f0.w);
            __half2 h2 = __floats2half2_rn(f1.x, f1.y);
            __half2 h3 = __floats2half2_rn(f1.z, f1.w);
            uint4 u = make_uint4(*(unsigned*)&h0, *(unsigned*)&h1,
                                 *(unsigned*)&h2, *(unsigned*)&h3);
            *(uint4*)(Ch + (size_t)e * cExp + (size_t)m * ldc + n0 + c8) = u;
        }
    } else {
#pragma unroll
        for (int i = 0; i < 16; i++) {
            int item = tid + i * 256;
            int row = item >> 5;
            int c4 = (item & 31) * 4;
            int m = m0 + row;
            if (m >= M) continue;
            float4 v = *(float4*)&sOut[row * 132 + c4];
            float* p = Cf + (size_t)e * cExp + (size_t)m * ldc + n0 + c4;
            if (EP == 2) {
                float4 old = *(float4*)p;
                v.x += old.x; v.y += old.y; v.z += old.z; v.w += old.w;
            }
            *(float4*)p = v;
        }
    }
}

// ======================= transpose + split convert (fp32 -> fp16 hi/lo) ======
__global__ void convT(const float* __restrict__ src, long long sExp, int K, int N,
                      fp16* __restrict__ th, fp16* __restrict__ tl, long long tExp) {
    __shared__ float t[32][33];
    int e = blockIdx.z;
    int k0 = blockIdx.x * 32, nn0 = blockIdx.y * 32;
    int tx = threadIdx.x, ty = threadIdx.y;   // 32 x 8
    const float* sp = src + (size_t)e * sExp;
#pragma unroll
    for (int r = 0; r < 4; r++) {
        int k = k0 + ty + r * 8;
        t[ty + r * 8][tx] = sp[(size_t)k * N + nn0 + tx];
    }
    __syncthreads();
#pragma unroll
    for (int r = 0; r < 4; r++) {
        int n = nn0 + ty + r * 8;
        float v = t[tx][ty + r * 8];
        fp16 hi = __float2half_rn(v);
        size_t o = (size_t)e * tExp + (size_t)n * K + k0 + tx;
        th[o] = hi;
        tl[o] = __float2half_rn(v - __half2float(hi));
    }
}

// ======================= pack Wq/Wk/Wv -> transposed fp16 planes [3C][C] ======
__global__ void pack_qkvT(const float* __restrict__ Wq,
                          const float* __restrict__ Wk,
                          const float* __restrict__ Wv,
                          fp16* __restrict__ th, fp16* __restrict__ tl) {
    int j = blockIdx.x;
    int which = j / CDIM, hs = j % CDIM;
    int h = hs / HSD, s = hs % HSD;
    const float* W = (which == 0) ? Wq : ((which == 1) ? Wk : Wv);
    for (int c = threadIdx.x; c < CDIM; c += 256) {
        float v = W[((size_t)h * CDIM + c) * HSD + s];
        fp16 hi = __float2half_rn(v);
        size_t o = (size_t)j * CDIM + c;
        th[o] = hi;
        tl[o] = __float2half_rn(v - __half2float(hi));
    }
}

// ======================= embedding =======================
__global__ void embed_kernel(const int* __restrict__ idx,
                             const float* __restrict__ tok,
                             const float* __restrict__ pos,
                             float* __restrict__ x) {
    int n = blockIdx.x;
    int t = n % TSEQ;
    int v = idx[n];
    for (int c = threadIdx.x; c < CDIM; c += blockDim.x)
        x[n * CDIM + c] = tok[v * CDIM + c] + pos[t * CDIM + c];
}

// ======================= layernorm (fp32 + fp16 hi/lo planes) ==============
__global__ void ln_kernel(const float* __restrict__ x,
                          const float* __restrict__ g,
                          const float* __restrict__ b,
                          float* __restrict__ out,
                          fp16* __restrict__ oh, fp16* __restrict__ ol) {
    int n = blockIdx.x;
    int tid = threadIdx.x;
    __shared__ float s1[256], s2[256];
    const float* xr = x + (size_t)n * CDIM;
    float a = 0.f, q = 0.f;
    for (int c = tid; c < CDIM; c += 256) { float v = xr[c]; a += v; q += v * v; }
    s1[tid] = a; s2[tid] = q;
    __syncthreads();
    for (int s = 128; s > 0; s >>= 1) {
        if (tid < s) { s1[tid] += s1[tid + s]; s2[tid] += s2[tid + s]; }
        __syncthreads();
    }
    float mean = s1[0] * (1.f / CDIM);
    float var  = s2[0] * (1.f / CDIM) - mean * mean;
    float r = rsqrtf(var + 1e-5f);
    for (int c = tid; c < CDIM; c += 256) {
        float o = (xr[c] - mean) * r * g[c] + b[c];
        size_t p = (size_t)n * CDIM + c;
        out[p] = o;
        fp16 hi = __float2half_rn(o);
        oh[p] = hi;
        ol[p] = __float2half_rn(o - __half2float(hi));
    }
}

// ======================= attention =======================
__global__ void attn_kernel(const float* __restrict__ qkv,
                            fp16* __restrict__ atth, fp16* __restrict__ attl) {
    int t = blockIdx.x, h = blockIdx.y, b = blockIdx.z;
    int tid = threadIdx.x;
    __shared__ float sc[TSEQ];
    __shared__ float qs[HSD];
    __shared__ float red[128];
    __shared__ float part[5 * HSD];

    int n0 = b * TSEQ;
    const float* Q = qkv + (size_t)(n0 + t) * (3 * CDIM) + h * HSD;
    if (tid < HSD) qs[tid] = Q[tid];
    __syncthreads();

    const float scale = 0.20412414523193154f;
    float lmax = -1e30f;
    for (int u = tid; u <= t; u += 128) {
        const float* Kp = qkv + (size_t)(n0 + u) * (3 * CDIM) + CDIM + h * HSD;
        float d = 0.f;
#pragma unroll
        for (int s = 0; s < HSD; s++) d += qs[s] * Kp[s];
        d *= scale;
        sc[u] = d;
        lmax = fmaxf(lmax, d);
    }
    red[tid] = lmax;
    __syncthreads();
    for (int s = 64; s > 0; s >>= 1) {
        if (tid < s) red[tid] = fmaxf(red[tid], red[tid + s]);
        __syncthreads();
    }
    float mx = red[0];
    __syncthreads();

    float lsum = 0.f;
    for (int u = tid; u <= t; u += 128) {
        float ev = expf(sc[u] - mx);
        sc[u] = ev;
        lsum += ev;
    }
    red[tid] = lsum;
    __syncthreads();
    for (int s = 64; s > 0; s >>= 1) {
        if (tid < s) red[tid] += red[tid + s];
        __syncthreads();
    }
    float inv = 1.f / red[0];
    __syncthreads();

    if (tid < 120) {
        int s = tid % HSD, gg = tid / HSD;
        float a = 0.f;
        for (int u = gg; u <= t; u += 5) {
            const float* Vp = qkv + (size_t)(n0 + u) * (3 * CDIM) + 2 * CDIM + h * HSD;
            a += sc[u] * Vp[s];
        }
        part[gg * HSD + s] = a;
    }
    __syncthreads();
    if (tid < HSD) {
        float a = (part[tid] + part[HSD + tid] + part[2 * HSD + tid]
                 + part[3 * HSD + tid] + part[4 * HSD + tid]) * inv;
        size_t o = (size_t)(n0 + t) * CDIM + h * HSD + tid;
        fp16 hi = __float2half_rn(a);
        atth[o] = hi;
        attl[o] = __float2half_rn(a - __half2float(hi));
    }
}

// ======================= gate softmax =======================
__global__ void gate_kernel(const float* __restrict__ h2,
                            const float* __restrict__ gw,
                            const float* __restrict__ gb,
                            float* __restrict__ gates) {
    int n = blockIdx.x;
    int e = threadIdx.x;
    const float* hr = h2 + (size_t)n * CDIM;
    float acc = gb[e];
    for (int c = 0; c < CDIM; c++) acc += hr[c] * gw[c * NE + e];
    float mx = acc;
    for (int o = 16; o > 0; o >>= 1) mx = fmaxf(mx, __shfl_xor_sync(0xFFFFFFFFu, mx, o));
    float ex = expf(acc - mx);
    float sm = ex;
    for (int o = 16; o > 0; o >>= 1) sm += __shfl_xor_sync(0xFFFFFFFFu, sm, o);
    gates[n * NE + e] = ex / sm;
}

// ======================= MoE combine =======================
__global__ void combine_kernel(const float* __restrict__ eo,
                               const float* __restrict__ gates,
                               float* __restrict__ x) {
    int n = blockIdx.x;
    __shared__ float gs[NE];
    if (threadIdx.x < NE) gs[threadIdx.x] = gates[n * NE + threadIdx.x];
    __syncthreads();
    for (int c = threadIdx.x; c < CDIM; c += blockDim.x) {
        float a = 0.f;
        const float* er = eo + (size_t)n * (NE * CDIM) + c;
#pragma unroll 8
        for (int e = 0; e < NE; e++) a += gs[e] * er[e * CDIM];
        x[(size_t)n * CDIM + c] += a;
    }
}

// ======================= scalar SGEMM (lm head only) =======================
__global__ void __launch_bounds__(256)
lm_head_kernel(const float* __restrict__ A, const float* __restrict__ B,
               const float* __restrict__ bias, float* __restrict__ C,
               int M, int N, int K) {
    __shared__ float As[64][17];
    __shared__ float Bs[16][64];
    int tid = threadIdx.x;
    int jTile = blockIdx.x * 64;
    int mTile = blockIdx.y * 64;
    int tx = tid & 15, ty = tid >> 4;

    float acc[4][4];
#pragma unroll
    for (int r = 0; r < 4; r++)
#pragma unroll
        for (int c = 0; c < 4; c++) acc[r][c] = 0.f;

    int aRow = tid >> 2, aK = (tid & 3) * 4;
    int bJ = tid & 63, bK0 = tid >> 6;

    for (int k0 = 0; k0 < K; k0 += 16) {
        int m = mTile + aRow;
        if (m < M) {
            float4 av = *(const float4*)(A + (size_t)m * K + k0 + aK);
            As[aRow][aK + 0] = av.x; As[aRow][aK + 1] = av.y;
            As[aRow][aK + 2] = av.z; As[aRow][aK + 3] = av.w;
        } else {
            As[aRow][aK + 0] = 0.f; As[aRow][aK + 1] = 0.f;
            As[aRow][aK + 2] = 0.f; As[aRow][aK + 3] = 0.f;
        }
#pragma unroll
        for (int i = 0; i < 4; i++) {
            int kk = bK0 + i * 4;
            Bs[kk][bJ] = (jTile + bJ < N)
                ? B[(size_t)(k0 + kk) * N + jTile + bJ] : 0.f;
        }
        __syncthreads();
#pragma unroll
        for (int k = 0; k < 16; k++) {
            float4 bv = *(const float4*)&Bs[k][tx * 4];
            float a0 = As[ty * 4 + 0][k], a1 = As[ty * 4 + 1][k];
            float a2 = As[ty * 4 + 2][k], a3 = As[ty * 4 + 3][k];
            acc[0][0] += a0 * bv.x; acc[0][1] += a0 * bv.y; acc[0][2] += a0 * bv.z; acc[0][3] += a0 * bv.w;
            acc[1][0] += a1 * bv.x; acc[1][1] += a1 * bv.y; acc[1][2] += a1 * bv.z; acc[1][3] += a1 * bv.w;
            acc[2][0] += a2 * bv.x; acc[2][1] += a2 * bv.y; acc[2][2] += a2 * bv.z; acc[2][3] += a2 * bv.w;
            acc[3][0] += a3 * bv.x; acc[3][1] += a3 * bv.y; acc[3][2] += a3 * bv.z; acc[3][3] += a3 * bv.w;
        }
        __syncthreads();
    }
#pragma unroll
    for (int r = 0; r < 4; r++) {
        int m = mTile + ty * 4 + r;
        if (m >= M) continue;
#pragma unroll
        for (int c = 0; c < 4; c++) {
            int j = jTile + tx * 4 + c;
            if (j >= N) continue;
            C[(size_t)m * N + j] = acc[r][c] + bias[j];
        }
    }
}

// ======================= launch =======================
extern "C" void kernel_launch(void* const* d_in, const int* in_sizes, int n_in,
                              void* d_out, int out_size) {
    const int*   idx    = (const int*)  d_in[0];
    const float* tok    = (const float*)d_in[1];
    const float* pos    = (const float*)d_in[2];
    const float* ln1_g  = (const float*)d_in[3];
    const float* ln1_b  = (const float*)d_in[4];
    const float* Wq     = (const float*)d_in[5];
    const float* Wk     = (const float*)d_in[6];
    const float* Wv     = (const float*)d_in[7];
    const float* Wo     = (const float*)d_in[8];
    const float* bo     = (const float*)d_in[9];
    const float* ln2_g  = (const float*)d_in[10];
    const float* ln2_b  = (const float*)d_in[11];
    const float* gate_w = (const float*)d_in[12];
    const float* gate_b = (const float*)d_in[13];
    const float* W1     = (const float*)d_in[14];
    const float* b1     = (const float*)d_in[15];
    const float* W2     = (const float*)d_in[16];
    const float* b2     = (const float*)d_in[17];
    const float* lnf_g  = (const float*)d_in[18];
    const float* lnf_b  = (const float*)d_in[19];
    const float* lm_w   = (const float*)d_in[20];
    const float* lm_b   = (const float*)d_in[21];
    float* out = (float*)d_out;

    float *x, *h, *qkv, *gates, *eo;
    fp16 *hh, *hl, *atth, *attl, *wpth, *wptl, *woth, *wotl;
    fp16 *w1th, *w1tl, *w2th, *w2tl, *hidh;
    cudaGetSymbolAddress((void**)&x,     g_x);
    cudaGetSymbolAddress((void**)&h,     g_h);
    cudaGetSymbolAddress((void**)&qkv,   g_qkv);
    cudaGetSymbolAddress((void**)&gates, g_gates);
    cudaGetSymbolAddress((void**)&eo,    g_eo);
    cudaGetSymbolAddress((void**)&hh,    g_hh);
    cudaGetSymbolAddress((void**)&hl,    g_hl);
    cudaGetSymbolAddress((void**)&atth,  g_atth);
    cudaGetSymbolAddress((void**)&attl,  g_attl);
    cudaGetSymbolAddress((void**)&wpth,  g_wpth);
    cudaGetSymbolAddress((void**)&wptl,  g_wptl);
    cudaGetSymbolAddress((void**)&woth,  g_woth);
    cudaGetSymbolAddress((void**)&wotl,  g_wotl);
    cudaGetSymbolAddress((void**)&w1th,  g_w1th);
    cudaGetSymbolAddress((void**)&w1tl,  g_w1tl);
    cudaGetSymbolAddress((void**)&w2th,  g_w2th);
    cudaGetSymbolAddress((void**)&w2tl,  g_w2tl);
    cudaGetSymbolAddress((void**)&hidh,  g_hidh);

    cudaFuncSetAttribute(mma_gemm<0,3>, cudaFuncAttributeMaxDynamicSharedMemorySize, SMEM_NT3);
    cudaFuncSetAttribute(mma_gemm<2,3>, cudaFuncAttributeMaxDynamicSharedMemorySize, SMEM_NT3);
    cudaFuncSetAttribute(mma_gemm<3,2>, cudaFuncAttributeMaxDynamicSharedMemorySize, SMEM_NT2);
    cudaFuncSetAttribute(mma_gemm<1,2>, cudaFuncAttributeMaxDynamicSharedMemorySize, SMEM_NT2);

    const int MT = (NTOK + 127) / 128;   // 7
    dim3 cblk(32, 8);

    // ---- pre-convert all weights (transpose + fp16 hi/lo split) ----
    for (int l = 0; l < NL; l++) {
        convT<<<dim3(CDIM / 32, F4D / 32, NE), cblk>>>(
            W1 + (size_t)l * NE * CDIM * F4D, (long long)CDIM * F4D, CDIM, F4D,
            w1th + (size_t)l * NE * F4D * CDIM, w1tl + (size_t)l * NE * F4D * CDIM,
            (long long)F4D * CDIM);
        convT<<<dim3(F4D / 32, CDIM / 32, NE), cblk>>>(
            W2 + (size_t)l * NE * F4D * CDIM, (long long)F4D * CDIM, F4D, CDIM,
            w2th + (size_t)l * NE * CDIM * F4D, w2tl + (size_t)l * NE * CDIM * F4D,
            (long long)CDIM * F4D);
        convT<<<dim3(CDIM / 32, CDIM / 32, 1), cblk>>>(
            Wo + (size_t)l * CDIM * CDIM, 0, CDIM, CDIM,
            woth + (size_t)l * CDIM * CDIM, wotl + (size_t)l * CDIM * CDIM, 0);
    }

    embed_kernel<<<NTOK, 256>>>(idx, tok, pos, x);

    for (int l = 0; l < NL; l++) {
        // --- attention ---
        ln_kernel<<<NTOK, 256>>>(x, ln1_g + l * CDIM, ln1_b + l * CDIM, h, hh, hl);
        pack_qkvT<<<3 * CDIM, 256>>>(
            Wq + (size_t)l * NH * CDIM * HSD,
            Wk + (size_t)l * NH * CDIM * HSD,
            Wv + (size_t)l * NH * CDIM * HSD, wpth, wptl);
        mma_gemm<0,3><<<dim3(MT * 18, 1), 256, SMEM_NT3>>>(
            hh, hl, CDIM, 0, wpth, wptl, CDIM, 0,
            nullptr, 0, qkv, nullptr, 3 * CDIM, 0,
            NTOK, 18, CDIM / 32);
        attn_kernel<<<dim3(TSEQ, NH, BSZ), 128>>>(qkv, atth, attl);
        mma_gemm<2,3><<<dim3(MT * 6, 1), 256, SMEM_NT3>>>(
            atth, attl, CDIM, 0,
            woth + (size_t)l * CDIM * CDIM, wotl + (size_t)l * CDIM * CDIM, CDIM, 0,
            bo + l * CDIM, 0, x, nullptr, CDIM, 0,
            NTOK, 6, CDIM / 32);

        // --- MoE ---
        ln_kernel<<<NTOK, 256>>>(x, ln2_g + l * CDIM, ln2_b + l * CDIM, h, hh, hl);
        gate_kernel<<<NTOK, 32>>>(h, gate_w + (size_t)l * CDIM * NE,
                                  gate_b + l * NE, gates);
        // up: hid = gelu(h @ W1_e + b1_e) -> fp16 hi plane
        mma_gemm<3,2><<<dim3(MT * (F4D / 128), NE), 256, SMEM_NT2>>>(
            hh, nullptr, CDIM, 0,
            w1th + (size_t)l * NE * F4D * CDIM, w1tl + (size_t)l * NE * F4D * CDIM,
            CDIM, (long long)F4D * CDIM,
            b1 + (size_t)l * NE * F4D, F4D,
            nullptr, hidh, (long long)NE * F4D, F4D,
            NTOK, F4D / 128, CDIM / 32);
        // down: eo = hid_e @ W2_e + b2_e
        mma_gemm<1,2><<<dim3(MT * (CDIM / 128), NE), 256, SMEM_NT2>>>(
            hidh, nullptr, (long long)NE * F4D, F4D,
            w2th + (size_t)l * NE * CDIM * F4D, w2tl + (size_t)l * NE * CDIM * F4D,
            F4D, (long long)CDIM * F4D,
            b2 + (size_t)l * NE * CDIM, CDIM,
            eo, nullptr, (long long)NE * CDIM, CDIM,
            NTOK, CDIM / 128, F4D / 32);
        combine_kernel<<<NTOK, 256>>>(eo, gates, x);
    }

    // --- final LN + lm head ---
    ln_kernel<<<NTOK, 256>>>(x, lnf_g, lnf_b, h, hh, hl);
    lm_head_kernel<<<dim3((NV + 63) / 64, (NTOK + 63) / 64), 256>>>(
        h, lm_w, lm_b, out, NTOK, NV, CDIM);
}